// round 3
// baseline (speedup 1.0000x reference)
#include <cuda_runtime.h>

#define LOG2E 1.4426950408889634f
#define NT 18          // 2304 / 128 tiles

// ---------------- scratch (__device__ globals; allocation-free rule) -------
__device__ float g_fused[32 * 2304];   // [sentence | scene_ctx | speaker_ctx]
__device__ float g_final[32 * 3840];   // [z | sentence_sh | scene_sh | speaker_sh]
__device__ float g_h[32 * 256];

// split-K partial buffers
#define PROJ_KC 24      // 768 / 32
#define PROJ_KCH 32
#define MLP_KC 120      // 3840 / 32
#define MLP_KCH 32
__device__ float g_pp[3 * PROJ_KC * 32 * 512];   // proj partials
__device__ float g_pm[MLP_KC * 32 * 256];        // mlp1 partials

// symmetric-attention partials: [b][tile][slot][row][num,den]
__device__ float g_ap[32 * NT * NT * 128 * 2];

__device__ __forceinline__ float ex2f(float x) {
    float y;
    asm("ex2.approx.f32 %0, %1;" : "=f"(y) : "f"(x));
    return y;
}

// ---------------------------------------------------------------------------
// Kernel 1: the two S=768 attentions + sentence copy, writing into g_fused.
// No max-subtraction: |q·k| <= ~20, unnormalized exps are safe in f32 and the
// softmax ratio is invariant.
// task 0: speaker_ctx = attn(q=oth, k=ts, v=ts)   -> g_fused[b][1536 + s]
// task 1: scene_ctx   = attn(q=ss,  k=ss, v=sd)   -> g_fused[b][ 768 + s]
// task 2: copy sentence                           -> g_fused[b][       s]
// grid (3, 32, 3), block 256
// ---------------------------------------------------------------------------
__global__ void attn_pre_kernel(const float* __restrict__ sent,
                                const float* __restrict__ ts,
                                const float* __restrict__ oth,
                                const float* __restrict__ sd,
                                const float* __restrict__ ss) {
    const int b    = blockIdx.y;
    const int task = blockIdx.z;
    const int s    = blockIdx.x * 256 + threadIdx.x;   // 0..767

    if (task == 2) {
        g_fused[b * 2304 + s] = sent[b * 768 + s];
        return;
    }

    const float* q = (task == 0) ? oth : ss;
    const float* k = (task == 0) ? ts  : ss;
    const float* v = (task == 0) ? ts  : sd;
    const int outoff = (task == 0) ? 1536 : 768;

    __shared__ __align__(16) float sk[768];
    __shared__ __align__(16) float sv[768];

    for (int t = threadIdx.x; t < 768; t += 256) {
        sk[t] = k[b * 768 + t];
        sv[t] = v[b * 768 + t];
    }
    __syncthreads();

    const float ql = q[b * 768 + s] * LOG2E;

    float num = 0.f, den = 0.f;
    for (int t = 0; t < 768; t += 4) {
        float4 kk = *reinterpret_cast<const float4*>(sk + t);
        float4 vv = *reinterpret_cast<const float4*>(sv + t);
        float w0 = ex2f(ql * kk.x);
        float w1 = ex2f(ql * kk.y);
        float w2 = ex2f(ql * kk.z);
        float w3 = ex2f(ql * kk.w);
        num = fmaf(w0, vv.x, num); den += w0;
        num = fmaf(w1, vv.y, num); den += w1;
        num = fmaf(w2, vv.z, num); den += w2;
        num = fmaf(w3, vv.w, num); den += w3;
    }
    g_fused[b * 2304 + outoff + s] = num / den;
}

// ---------------------------------------------------------------------------
// Kernel 2a: symmetric fused self-attention tiles.
// E[s,t] = exp(f_s * f_t) is symmetric (q=k=v). Each block handles tile pair
// (I,J), I<=J, one batch: 128x128 exps computed ONCE, accumulated into both
// row-side (tile I) and col-side (tile J) partials.
// grid (NT, NT, 32) with I>J blocks exiting; block 256 = 16x16 threads,
// each thread owns an 8x8 exp micro-tile in registers.
// Partial slots: pair (I,J) -> tile I slot J (rows) and tile J slot I (cols);
// diagonal writes only row side. Every tile gets exactly NT slots.
// ---------------------------------------------------------------------------
__global__ void __launch_bounds__(256) attn_fused_sym() {
    const int I = blockIdx.x, J = blockIdx.y, b = blockIdx.z;
    if (I > J) return;
    const bool diag = (I == J);

    __shared__ __align__(16) float fI[128];
    __shared__ __align__(16) float fJ[128];
    __shared__ float2 s2[128][17];   // padded

    const int tid = threadIdx.x;
    const int r = tid >> 4, c = tid & 15;

    if (tid < 128) fI[tid] = g_fused[b * 2304 + I * 128 + tid];
    else           fJ[tid - 128] = g_fused[b * 2304 + J * 128 + (tid - 128)];
    __syncthreads();

    float fs[8], fsl[8], ft[8];
#pragma unroll
    for (int i = 0; i < 8; i++) { fs[i] = fI[r * 8 + i]; fsl[i] = fs[i] * LOG2E; }
#pragma unroll
    for (int j = 0; j < 8; j++) ft[j] = fJ[c * 8 + j];

    float nr[8], dr[8], nc[8], dc[8];
#pragma unroll
    for (int i = 0; i < 8; i++) { nr[i] = 0.f; dr[i] = 0.f; nc[i] = 0.f; dc[i] = 0.f; }

#pragma unroll
    for (int i = 0; i < 8; i++) {
#pragma unroll
        for (int j = 0; j < 8; j++) {
            float E = ex2f(fsl[i] * ft[j]);
            nr[i] = fmaf(E, ft[j], nr[i]);
            dr[i] += E;
            nc[j] = fmaf(E, fs[i], nc[j]);
            dc[j] += E;
        }
    }

    // row-side reduction over the 16 c-threads -> tile I, slot J
#pragma unroll
    for (int i = 0; i < 8; i++) s2[r * 8 + i][c] = make_float2(nr[i], dr[i]);
    __syncthreads();
    if (tid < 128) {
        float2 a = s2[tid][0];
#pragma unroll
        for (int kk = 1; kk < 16; kk++) {
            float2 p = s2[tid][kk];
            a.x += p.x; a.y += p.y;
        }
        float* dst = g_ap + (((size_t)(b * NT + I) * NT + J) * 128 + tid) * 2;
        dst[0] = a.x; dst[1] = a.y;
    }

    if (!diag) {
        __syncthreads();
        // col-side reduction over the 16 r-threads -> tile J, slot I
#pragma unroll
        for (int j = 0; j < 8; j++) s2[c * 8 + j][r] = make_float2(nc[j], dc[j]);
        __syncthreads();
        if (tid < 128) {
            float2 a = s2[tid][0];
#pragma unroll
            for (int kk = 1; kk < 16; kk++) {
                float2 p = s2[tid][kk];
                a.x += p.x; a.y += p.y;
            }
            float* dst = g_ap + (((size_t)(b * NT + J) * NT + I) * 128 + tid) * 2;
            dst[0] = a.x; dst[1] = a.y;
        }
    }
}

// Kernel 2b: reduce attention partials -> z in g_final.  grid 288, block 256
__global__ void attn_fused_reduce() {
    const int idx = blockIdx.x * 256 + threadIdx.x;   // 0..73727
    const int b = idx / 2304;
    const int s = idx % 2304;
    const int T = s >> 7, row = s & 127;

    const float2* ap = reinterpret_cast<const float2*>(g_ap)
                     + ((size_t)(b * NT + T) * NT) * 128 + row;
    float num = 0.f, den = 0.f;
#pragma unroll
    for (int slot = 0; slot < NT; slot++) {
        float2 p = ap[slot * 128];
        num += p.x; den += p.y;
    }
    g_final[b * 3840 + s] = num / den;
}

// ---------------------------------------------------------------------------
// Kernel 3a: split-K shared projections.
// grid (PROJ_KC, 4, 3) = (kchunk, jtile, task), block 128 (j within tile).
// ---------------------------------------------------------------------------
__global__ void shared_proj_split(const float* __restrict__ sent,
                                  const float* __restrict__ Wsh) {
    const int kc   = blockIdx.x;
    const int jt   = blockIdx.y;
    const int task = blockIdx.z;
    const int j    = jt * 128 + threadIdx.x;      // 0..511
    const int i0   = kc * PROJ_KCH;

    __shared__ __align__(16) float xs[PROJ_KCH][36];  // [i][b], padded

    for (int e = threadIdx.x; e < PROJ_KCH * 32; e += 128) {
        int b = e >> 5, i = e & 31;
        float v = (task == 0) ? sent[b * 768 + i0 + i]
                              : g_fused[b * 2304 + 768 * task + i0 + i];
        xs[i][b] = v;
    }
    __syncthreads();

    float acc[32];
#pragma unroll
    for (int b = 0; b < 32; b++) acc[b] = 0.f;

    for (int i = 0; i < PROJ_KCH; i++) {
        float w = Wsh[(i0 + i) * 512 + j];
#pragma unroll
        for (int b4 = 0; b4 < 8; b4++) {
            float4 x = *reinterpret_cast<const float4*>(&xs[i][b4 * 4]);
            acc[b4 * 4 + 0] = fmaf(x.x, w, acc[b4 * 4 + 0]);
            acc[b4 * 4 + 1] = fmaf(x.y, w, acc[b4 * 4 + 1]);
            acc[b4 * 4 + 2] = fmaf(x.z, w, acc[b4 * 4 + 2]);
            acc[b4 * 4 + 3] = fmaf(x.w, w, acc[b4 * 4 + 3]);
        }
    }

#pragma unroll
    for (int b = 0; b < 32; b++)
        g_pp[(((task * PROJ_KC) + kc) * 32 + b) * 512 + j] = acc[b];
}

// Kernel 3b: reduce proj partials + bias -> g_final.  grid 192, block 256
__global__ void proj_reduce(const float* __restrict__ bsh) {
    const int o = blockIdx.x * 256 + threadIdx.x;   // 0..49151
    const int task = o >> 14;
    const int r = o & 16383;
    const int b = r >> 9;
    const int j = r & 511;

    float a0 = bsh[j], a1 = 0.f, a2 = 0.f, a3 = 0.f;
#pragma unroll
    for (int kc = 0; kc < PROJ_KC; kc += 4) {
        a0 += g_pp[(((task * PROJ_KC) + kc + 0) * 32 + b) * 512 + j];
        a1 += g_pp[(((task * PROJ_KC) + kc + 1) * 32 + b) * 512 + j];
        a2 += g_pp[(((task * PROJ_KC) + kc + 2) * 32 + b) * 512 + j];
        a3 += g_pp[(((task * PROJ_KC) + kc + 3) * 32 + b) * 512 + j];
    }
    g_final[b * 3840 + 2304 + task * 512 + j] = (a0 + a1) + (a2 + a3);
}

// ---------------------------------------------------------------------------
// Kernel 4a: split-K mlp1.  grid (MLP_KC), block 256 (j = tid).
// ---------------------------------------------------------------------------
__global__ void mlp1_split(const float* __restrict__ W1) {
    const int kc = blockIdx.x;
    const int i0 = kc * MLP_KCH;
    const int j  = threadIdx.x;   // 0..255

    __shared__ __align__(16) float xs[MLP_KCH][36];

    for (int e = threadIdx.x; e < MLP_KCH * 32; e += 256) {
        int b = e >> 5, i = e & 31;
        xs[i][b] = g_final[b * 3840 + i0 + i];
    }
    __syncthreads();

    float acc[32];
#pragma unroll
    for (int b = 0; b < 32; b++) acc[b] = 0.f;

    for (int i = 0; i < MLP_KCH; i++) {
        float w = W1[(i0 + i) * 256 + j];
#pragma unroll
        for (int b4 = 0; b4 < 8; b4++) {
            float4 x = *reinterpret_cast<const float4*>(&xs[i][b4 * 4]);
            acc[b4 * 4 + 0] = fmaf(x.x, w, acc[b4 * 4 + 0]);
            acc[b4 * 4 + 1] = fmaf(x.y, w, acc[b4 * 4 + 1]);
            acc[b4 * 4 + 2] = fmaf(x.z, w, acc[b4 * 4 + 2]);
            acc[b4 * 4 + 3] = fmaf(x.w, w, acc[b4 * 4 + 3]);
        }
    }

#pragma unroll
    for (int b = 0; b < 32; b++)
        g_pm[(kc * 32 + b) * 256 + j] = acc[b];
}

// Kernel 4b: reduce mlp1 partials + bias + relu -> g_h.  grid 32, block 256
__global__ void mlp1_reduce(const float* __restrict__ b1) {
    const int o = blockIdx.x * 256 + threadIdx.x;   // 0..8191
    const int b = o >> 8;
    const int j = o & 255;

    float a0 = b1[j], a1 = 0.f, a2 = 0.f, a3 = 0.f;
#pragma unroll
    for (int kc = 0; kc < MLP_KC; kc += 4) {
        a0 += g_pm[((kc + 0) * 32 + b) * 256 + j];
        a1 += g_pm[((kc + 1) * 32 + b) * 256 + j];
        a2 += g_pm[((kc + 2) * 32 + b) * 256 + j];
        a3 += g_pm[((kc + 3) * 32 + b) * 256 + j];
    }
    g_h[o] = fmaxf((a0 + a1) + (a2 + a3), 0.f);
}

// ---------------------------------------------------------------------------
// Kernel 5: out = sigmoid(h @ W2 + b2).  grid 1, block 256 (224 active)
// ---------------------------------------------------------------------------
__global__ void mlp2_kernel(const float* __restrict__ W2,
                            const float* __restrict__ b2,
                            float* __restrict__ out) {
    const int tid = threadIdx.x;
    if (tid >= 224) return;
    const int b = tid / 7, c = tid % 7;

    float a0 = b2[c], a1 = 0.f, a2 = 0.f, a3 = 0.f;
    for (int jj = 0; jj < 256; jj += 4) {
        a0 = fmaf(g_h[b * 256 + jj + 0], W2[(jj + 0) * 7 + c], a0);
        a1 = fmaf(g_h[b * 256 + jj + 1], W2[(jj + 1) * 7 + c], a1);
        a2 = fmaf(g_h[b * 256 + jj + 2], W2[(jj + 2) * 7 + c], a2);
        a3 = fmaf(g_h[b * 256 + jj + 3], W2[(jj + 3) * 7 + c], a3);
    }
    float x = (a0 + a1) + (a2 + a3);
    out[b * 7 + c] = 1.f / (1.f + __expf(-x));
}

extern "C" void kernel_launch(void* const* d_in, const int* in_sizes, int n_in,
                              void* d_out, int out_size) {
    const float* sent = (const float*)d_in[0];
    const float* ts   = (const float*)d_in[1];
    const float* oth  = (const float*)d_in[2];
    const float* sd   = (const float*)d_in[3];
    const float* ss   = (const float*)d_in[4];
    const float* Wsh  = (const float*)d_in[5];
    const float* bsh  = (const float*)d_in[6];
    const float* W1   = (const float*)d_in[7];
    const float* b1   = (const float*)d_in[8];
    const float* W2   = (const float*)d_in[9];
    const float* b2   = (const float*)d_in[10];
    float* out = (float*)d_out;

    attn_pre_kernel<<<dim3(3, 32, 3), 256>>>(sent, ts, oth, sd, ss);
    attn_fused_sym<<<dim3(NT, NT, 32), 256>>>();
    attn_fused_reduce<<<288, 256>>>();
    shared_proj_split<<<dim3(PROJ_KC, 4, 3), 128>>>(sent, Wsh);
    proj_reduce<<<192, 256>>>(bsh);
    mlp1_split<<<MLP_KC, 256>>>(W1);
    mlp1_reduce<<<32, 256>>>(b1);
    mlp2_kernel<<<1, 256>>>(W2, b2, out);
}

// round 5
// speedup vs baseline: 1.1424x; 1.1424x over previous
#include <cuda_runtime.h>

#define LOG2E 1.4426950408889634f
#define NT 18          // 2304 / 128 tiles

#define PROJ_KC 48     // 768 / 16
#define PROJ_KCH 16
#define MLP_KC 240     // 3840 / 16
#define MLP_KCH 16

// ---------------- scratch (__device__ globals; allocation-free rule) -------
__device__ float g_fused[32 * 2304];   // [sentence | scene_ctx | speaker_ctx]
__device__ float g_h_part[MLP_KC * 32 * 256];              // mlp1 partials [kc][b][j]
__device__ float g_pp[3 * PROJ_KC * 512 * 32];             // proj partials [task][kc][j][b]
__device__ float g_ap[32 * NT * NT * 128 * 2];             // attn partials [b][tile][slot][row][2]

typedef unsigned long long ull;

__device__ __forceinline__ float ex2f(float x) {
    float y; asm("ex2.approx.f32 %0, %1;" : "=f"(y) : "f"(x)); return y;
}
__device__ __forceinline__ ull pk2(float lo, float hi) {
    ull r; asm("mov.b64 %0, {%1, %2};" : "=l"(r) : "f"(lo), "f"(hi)); return r;
}
__device__ __forceinline__ void upk2(ull p, float& lo, float& hi) {
    asm("mov.b64 {%0, %1}, %2;" : "=f"(lo), "=f"(hi) : "l"(p));
}
__device__ __forceinline__ ull mul2(ull a, ull b) {
    ull r; asm("mul.rn.f32x2 %0, %1, %2;" : "=l"(r) : "l"(a), "l"(b)); return r;
}
__device__ __forceinline__ ull fma2(ull a, ull b, ull c) {
    ull r; asm("fma.rn.f32x2 %0, %1, %2, %3;" : "=l"(r) : "l"(a), "l"(b), "l"(c)); return r;
}
__device__ __forceinline__ ull add2(ull a, ull b) {
    ull r; asm("add.rn.f32x2 %0, %1, %2;" : "=l"(r) : "l"(a), "l"(b)); return r;
}

// ---------------------------------------------------------------------------
// Kernel 1: two S=768 attentions + sentence copy -> g_fused.
// No max-subtraction (|q·k| small; softmax ratio invariant). MUFU-bound.
// grid (3, 32, 3), block 256
// ---------------------------------------------------------------------------
__global__ void attn_pre_kernel(const float* __restrict__ sent,
                                const float* __restrict__ ts,
                                const float* __restrict__ oth,
                                const float* __restrict__ sd,
                                const float* __restrict__ ss) {
    const int b    = blockIdx.y;
    const int task = blockIdx.z;
    const int s    = blockIdx.x * 256 + threadIdx.x;

    if (task == 2) {
        g_fused[b * 2304 + s] = sent[b * 768 + s];
        return;
    }

    const float* q = (task == 0) ? oth : ss;
    const float* k = (task == 0) ? ts  : ss;
    const float* v = (task == 0) ? ts  : sd;
    const int outoff = (task == 0) ? 1536 : 768;

    __shared__ __align__(16) float sk[768];
    __shared__ __align__(16) float sv[768];

    for (int t = threadIdx.x; t < 768; t += 256) {
        sk[t] = k[b * 768 + t];
        sv[t] = v[b * 768 + t];
    }
    __syncthreads();

    const float ql = q[b * 768 + s] * LOG2E;

    float num = 0.f, den = 0.f;
    for (int t = 0; t < 768; t += 4) {
        float4 kk = *reinterpret_cast<const float4*>(sk + t);
        float4 vv = *reinterpret_cast<const float4*>(sv + t);
        float w0 = ex2f(ql * kk.x);
        float w1 = ex2f(ql * kk.y);
        float w2 = ex2f(ql * kk.z);
        float w3 = ex2f(ql * kk.w);
        num = fmaf(w0, vv.x, num); den += w0;
        num = fmaf(w1, vv.y, num); den += w1;
        num = fmaf(w2, vv.z, num); den += w2;
        num = fmaf(w3, vv.w, num); den += w3;
    }
    g_fused[b * 2304 + outoff + s] = num / den;
}

// ---------------------------------------------------------------------------
// Kernel 2: symmetric fused self-attention tiles, f32x2-packed accumulation.
// E[s,t]=exp(f_s f_t) symmetric (q=k=v). Block = tile pair (I<=J) for batch b;
// 256 threads as 16x16, each owns an 8x8 exp micro-tile, j in pairs.
// exp arg uses log2e-scaled fs ONLY (fsl2); numerators use UNSCALED fs2/ft2.
// ---------------------------------------------------------------------------
__global__ void __launch_bounds__(256) attn_fused_sym() {
    const int I = blockIdx.x, J = blockIdx.y, b = blockIdx.z;
    if (I > J) return;
    const bool diag = (I == J);

    __shared__ __align__(16) float fI[128];
    __shared__ __align__(16) float fJ[128];
    __shared__ float2 s2[128][17];

    const int tid = threadIdx.x;
    const int r = tid >> 4, c = tid & 15;

    if (tid < 128) fI[tid] = g_fused[b * 2304 + I * 128 + tid];
    else           fJ[tid - 128] = g_fused[b * 2304 + J * 128 + (tid - 128)];
    __syncthreads();

    ull fsl2[8];   // (fs_i*log2e, fs_i*log2e)  -- exp-arg side
    ull fs2[8];    // (fs_i, fs_i)              -- numerator side
    ull ft2[4];    // (ft_{2m}, ft_{2m+1})      -- arg other-operand AND numerator
#pragma unroll
    for (int i = 0; i < 8; i++) {
        float f = fI[r * 8 + i];
        fs2[i]  = pk2(f, f);
        fsl2[i] = pk2(f * LOG2E, f * LOG2E);
    }
#pragma unroll
    for (int m = 0; m < 4; m++)
        ft2[m] = pk2(fJ[c * 8 + 2 * m], fJ[c * 8 + 2 * m + 1]);

    ull nr2[8], dr2[8], nc2[4], dc2[4];
#pragma unroll
    for (int i = 0; i < 8; i++) { nr2[i] = 0ULL; dr2[i] = 0ULL; }
#pragma unroll
    for (int m = 0; m < 4; m++) { nc2[m] = 0ULL; dc2[m] = 0ULL; }

#pragma unroll
    for (int i = 0; i < 8; i++) {
#pragma unroll
        for (int m = 0; m < 4; m++) {
            ull p = mul2(fsl2[i], ft2[m]);          // fs*ft*log2e  (correct domain)
            float a0, a1; upk2(p, a0, a1);
            ull E2 = pk2(ex2f(a0), ex2f(a1));       // (E_j0, E_j1)
            nr2[i] = fma2(E2, ft2[m], nr2[i]);      // row num (natural domain)
            dr2[i] = add2(dr2[i], E2);              // row den
            nc2[m] = fma2(E2, fs2[i], nc2[m]);      // col num
            dc2[m] = add2(dc2[m], E2);              // col den
        }
    }

    // row-side reduce over 16 c-threads -> tile I, slot J
#pragma unroll
    for (int i = 0; i < 8; i++) {
        float nx, ny, dx, dy;
        upk2(nr2[i], nx, ny);
        upk2(dr2[i], dx, dy);
        s2[r * 8 + i][c] = make_float2(nx + ny, dx + dy);
    }
    __syncthreads();
    if (tid < 128) {
        float2 a = s2[tid][0];
#pragma unroll
        for (int kk = 1; kk < 16; kk++) { float2 p = s2[tid][kk]; a.x += p.x; a.y += p.y; }
        float* dst = g_ap + (((size_t)(b * NT + I) * NT + J) * 128 + tid) * 2;
        dst[0] = a.x; dst[1] = a.y;
    }

    if (!diag) {
        __syncthreads();
        // col-side reduce over 16 r-threads -> tile J, slot I
#pragma unroll
        for (int m = 0; m < 4; m++) {
            float n0, n1, d0, d1;
            upk2(nc2[m], n0, n1);
            upk2(dc2[m], d0, d1);
            s2[c * 8 + 2 * m][r]     = make_float2(n0, d0);
            s2[c * 8 + 2 * m + 1][r] = make_float2(n1, d1);
        }
        __syncthreads();
        if (tid < 128) {
            float2 a = s2[tid][0];
#pragma unroll
            for (int kk = 1; kk < 16; kk++) { float2 p = s2[tid][kk]; a.x += p.x; a.y += p.y; }
            float* dst = g_ap + (((size_t)(b * NT + J) * NT + I) * 128 + tid) * 2;
            dst[0] = a.x; dst[1] = a.y;
        }
    }
}

// ---------------------------------------------------------------------------
// Kernel 3: split-K shared projections. grid (PROJ_KC, 4, 3), block 128.
// Output layout [task][kc][j][b]: per-thread contiguous 32-float run.
// ---------------------------------------------------------------------------
__global__ void shared_proj_split(const float* __restrict__ sent,
                                  const float* __restrict__ Wsh) {
    const int kc   = blockIdx.x;
    const int jt   = blockIdx.y;
    const int task = blockIdx.z;
    const int j    = jt * 128 + threadIdx.x;      // 0..511
    const int i0   = kc * PROJ_KCH;

    __shared__ __align__(16) float xs[PROJ_KCH][36];

    for (int e = threadIdx.x; e < PROJ_KCH * 32; e += 128) {
        int b = e & 31, i = e >> 5;     // i in [0,16), b in [0,32)
        xs[i][b] = (task == 0) ? sent[b * 768 + i0 + i]
                               : g_fused[b * 2304 + 768 * task + i0 + i];
    }
    __syncthreads();

    float acc[32];
#pragma unroll
    for (int b = 0; b < 32; b++) acc[b] = 0.f;

#pragma unroll
    for (int i = 0; i < PROJ_KCH; i++) {
        float w = Wsh[(i0 + i) * 512 + j];
#pragma unroll
        for (int b4 = 0; b4 < 8; b4++) {
            float4 x = *reinterpret_cast<const float4*>(&xs[i][b4 * 4]);
            acc[b4 * 4 + 0] = fmaf(x.x, w, acc[b4 * 4 + 0]);
            acc[b4 * 4 + 1] = fmaf(x.y, w, acc[b4 * 4 + 1]);
            acc[b4 * 4 + 2] = fmaf(x.z, w, acc[b4 * 4 + 2]);
            acc[b4 * 4 + 3] = fmaf(x.w, w, acc[b4 * 4 + 3]);
        }
    }

    float* dst = g_pp + (((size_t)(task * PROJ_KC + kc) * 512) + j) * 32;
#pragma unroll
    for (int b4 = 0; b4 < 8; b4++)
        *reinterpret_cast<float4*>(dst + b4 * 4) =
            make_float4(acc[b4 * 4], acc[b4 * 4 + 1], acc[b4 * 4 + 2], acc[b4 * 4 + 3]);
}

// ---------------------------------------------------------------------------
// Kernel 4: fused assemble + split-K mlp1.  grid MLP_KC, block 256.
// Load phase reconstructs final[i][b] directly from attention/proj partials
// (each element consumed by exactly one block). Then 16K x 32b x 256j FMAs.
// ---------------------------------------------------------------------------
__global__ void __launch_bounds__(256) mlp1_split(const float* __restrict__ W1,
                                                  const float* __restrict__ bsh) {
    const int kc = blockIdx.x;
    const int i0 = kc * MLP_KCH;
    const int j  = threadIdx.x;

    __shared__ __align__(16) float xs[MLP_KCH][36];

    for (int e = threadIdx.x; e < MLP_KCH * 32; e += 256) {
        int ii = e >> 5, b = e & 31;
        int gi = i0 + ii;
        float val;
        if (gi < 2304) {
            const float2* ap = reinterpret_cast<const float2*>(g_ap)
                             + ((size_t)(b * NT + (gi >> 7)) * NT) * 128 + (gi & 127);
            float num = 0.f, den = 0.f;
#pragma unroll
            for (int s = 0; s < NT; s++) { float2 p = ap[s * 128]; num += p.x; den += p.y; }
            val = num / den;
        } else {
            int t = gi - 2304;
            int task = t >> 9, jj = t & 511;
            float a = bsh[jj];
            const float* pp = g_pp + (((size_t)(task * PROJ_KC) * 512) + jj) * 32 + b;
#pragma unroll
            for (int s = 0; s < PROJ_KC; s++) a += pp[(size_t)s * 512 * 32];
            val = a;
        }
        xs[ii][b] = val;
    }
    __syncthreads();

    float acc[32];
#pragma unroll
    for (int b = 0; b < 32; b++) acc[b] = 0.f;

#pragma unroll
    for (int i = 0; i < MLP_KCH; i++) {
        float w = W1[(i0 + i) * 256 + j];
#pragma unroll
        for (int b4 = 0; b4 < 8; b4++) {
            float4 x = *reinterpret_cast<const float4*>(&xs[i][b4 * 4]);
            acc[b4 * 4 + 0] = fmaf(x.x, w, acc[b4 * 4 + 0]);
            acc[b4 * 4 + 1] = fmaf(x.y, w, acc[b4 * 4 + 1]);
            acc[b4 * 4 + 2] = fmaf(x.z, w, acc[b4 * 4 + 2]);
            acc[b4 * 4 + 3] = fmaf(x.w, w, acc[b4 * 4 + 3]);
        }
    }

#pragma unroll
    for (int b = 0; b < 32; b++)
        g_h_part[((size_t)kc * 32 + b) * 256 + j] = acc[b];
}

// ---------------------------------------------------------------------------
// Kernel 5: reduce mlp1 partials + bias + relu, then mlp2 + sigmoid.
// grid 32 (batch), block 256 (j).
// ---------------------------------------------------------------------------
__global__ void mlp_tail(const float* __restrict__ b1,
                         const float* __restrict__ W2,
                         const float* __restrict__ b2,
                         float* __restrict__ out) {
    const int b = blockIdx.x;
    const int j = threadIdx.x;

    float a0 = b1[j], a1 = 0.f, a2 = 0.f, a3 = 0.f;
#pragma unroll 4
    for (int kc = 0; kc < MLP_KC; kc += 4) {
        a0 += g_h_part[((size_t)(kc + 0) * 32 + b) * 256 + j];
        a1 += g_h_part[((size_t)(kc + 1) * 32 + b) * 256 + j];
        a2 += g_h_part[((size_t)(kc + 2) * 32 + b) * 256 + j];
        a3 += g_h_part[((size_t)(kc + 3) * 32 + b) * 256 + j];
    }
    __shared__ float h[256];
    h[j] = fmaxf((a0 + a1) + (a2 + a3), 0.f);
    __syncthreads();

    const int w = j >> 5, lane = j & 31;
    if (w < 7) {
        float s = 0.f;
#pragma unroll
        for (int q = 0; q < 8; q++) s = fmaf(h[q * 32 + lane], W2[(q * 32 + lane) * 7 + w], s);
#pragma unroll
        for (int o = 16; o > 0; o >>= 1) s += __shfl_xor_sync(0xffffffffu, s, o);
        if (lane == 0) out[b * 7 + w] = 1.f / (1.f + __expf(-(s + b2[w])));
    }
}

extern "C" void kernel_launch(void* const* d_in, const int* in_sizes, int n_in,
                              void* d_out, int out_size) {
    const float* sent = (const float*)d_in[0];
    const float* ts   = (const float*)d_in[1];
    const float* oth  = (const float*)d_in[2];
    const float* sd   = (const float*)d_in[3];
    const float* ss   = (const float*)d_in[4];
    const float* Wsh  = (const float*)d_in[5];
    const float* bsh  = (const float*)d_in[6];
    const float* W1   = (const float*)d_in[7];
    const float* b1   = (const float*)d_in[8];
    const float* W2   = (const float*)d_in[9];
    const float* b2   = (const float*)d_in[10];
    float* out = (float*)d_out;

    static cudaStream_t s1 = nullptr;
    static cudaEvent_t ev_pre = nullptr, ev_sym = nullptr;
    if (s1 == nullptr) {
        cudaStreamCreateWithFlags(&s1, cudaStreamNonBlocking);
        cudaEventCreateWithFlags(&ev_pre, cudaEventDisableTiming);
        cudaEventCreateWithFlags(&ev_sym, cudaEventDisableTiming);
    }

    attn_pre_kernel<<<dim3(3, 32, 3), 256>>>(sent, ts, oth, sd, ss);
    cudaEventRecord(ev_pre, 0);
    cudaStreamWaitEvent(s1, ev_pre, 0);
    attn_fused_sym<<<dim3(NT, NT, 32), 256, 0, s1>>>();
    cudaEventRecord(ev_sym, s1);
    shared_proj_split<<<dim3(PROJ_KC, 4, 3), 128>>>(sent, Wsh);   // overlaps sym
    cudaStreamWaitEvent(0, ev_sym, 0);
    mlp1_split<<<MLP_KC, 256>>>(W1, bsh);
    mlp_tail<<<32, 256>>>(b1, W2, b2, out);
}

// round 6
// speedup vs baseline: 1.2303x; 1.0769x over previous
#include <cuda_runtime.h>

#define LOG2E 1.4426950408889634f
#define NT 18          // 2304 / 128 tiles

#define PROJ_KC 48     // 768 / 16
#define PROJ_KCH 16
#define MLP_KC 120     // 3840 / 32
#define MLP_KCH 32

// ---------------- scratch (__device__ globals; allocation-free rule) -------
__device__ float g_fused[32 * 2304];                 // [sentence | scene | speaker]
__device__ float g_finalT[3840 * 32];                // transposed final [i][b]
__device__ float g_h_part[MLP_KC * 32 * 256];        // mlp1 partials [kc][b][j]
__device__ float g_pp[3 * PROJ_KC * 32 * 512];       // proj partials [task][kc][b][j]
__device__ float g_ap[32 * NT * NT * 128 * 2];       // attn partials [b][tile][slot][row][2]

typedef unsigned long long ull;

__device__ __forceinline__ float ex2f(float x) {
    float y; asm("ex2.approx.f32 %0, %1;" : "=f"(y) : "f"(x)); return y;
}
__device__ __forceinline__ ull pk2(float lo, float hi) {
    ull r; asm("mov.b64 %0, {%1, %2};" : "=l"(r) : "f"(lo), "f"(hi)); return r;
}
__device__ __forceinline__ void upk2(ull p, float& lo, float& hi) {
    asm("mov.b64 {%0, %1}, %2;" : "=f"(lo), "=f"(hi) : "l"(p));
}
__device__ __forceinline__ ull mul2(ull a, ull b) {
    ull r; asm("mul.rn.f32x2 %0, %1, %2;" : "=l"(r) : "l"(a), "l"(b)); return r;
}
__device__ __forceinline__ ull fma2(ull a, ull b, ull c) {
    ull r; asm("fma.rn.f32x2 %0, %1, %2, %3;" : "=l"(r) : "l"(a), "l"(b), "l"(c)); return r;
}
__device__ __forceinline__ ull add2(ull a, ull b) {
    ull r; asm("add.rn.f32x2 %0, %1, %2;" : "=l"(r) : "l"(a), "l"(b)); return r;
}

// ---------------------------------------------------------------------------
// Kernel 1: two S=768 attentions + sentence copy -> g_fused.
// grid (3, 32, 3), block 256
// ---------------------------------------------------------------------------
__global__ void attn_pre_kernel(const float* __restrict__ sent,
                                const float* __restrict__ ts,
                                const float* __restrict__ oth,
                                const float* __restrict__ sd,
                                const float* __restrict__ ss) {
    const int b    = blockIdx.y;
    const int task = blockIdx.z;
    const int s    = blockIdx.x * 256 + threadIdx.x;

    if (task == 2) {
        g_fused[b * 2304 + s] = sent[b * 768 + s];
        return;
    }

    const float* q = (task == 0) ? oth : ss;
    const float* k = (task == 0) ? ts  : ss;
    const float* v = (task == 0) ? ts  : sd;
    const int outoff = (task == 0) ? 1536 : 768;

    __shared__ __align__(16) float sk[768];
    __shared__ __align__(16) float sv[768];

    for (int t = threadIdx.x; t < 768; t += 256) {
        sk[t] = k[b * 768 + t];
        sv[t] = v[b * 768 + t];
    }
    __syncthreads();

    const float ql = q[b * 768 + s] * LOG2E;

    float num = 0.f, den = 0.f;
    for (int t = 0; t < 768; t += 4) {
        float4 kk = *reinterpret_cast<const float4*>(sk + t);
        float4 vv = *reinterpret_cast<const float4*>(sv + t);
        float w0 = ex2f(ql * kk.x);
        float w1 = ex2f(ql * kk.y);
        float w2 = ex2f(ql * kk.z);
        float w3 = ex2f(ql * kk.w);
        num = fmaf(w0, vv.x, num); den += w0;
        num = fmaf(w1, vv.y, num); den += w1;
        num = fmaf(w2, vv.z, num); den += w2;
        num = fmaf(w3, vv.w, num); den += w3;
    }
    g_fused[b * 2304 + outoff + s] = num / den;
}

// ---------------------------------------------------------------------------
// Kernel 2: symmetric fused self-attention tiles, f32x2-packed accumulation.
// E[s,t]=exp(f_s f_t) symmetric (q=k=v). exp arg uses log2e-scaled fs only.
// grid (NT, NT, 32), I>J blocks exit; block 256 = 16x16, 8x8 micro-tile.
// ---------------------------------------------------------------------------
__global__ void __launch_bounds__(256) attn_fused_sym() {
    const int I = blockIdx.x, J = blockIdx.y, b = blockIdx.z;
    if (I > J) return;
    const bool diag = (I == J);

    __shared__ __align__(16) float fI[128];
    __shared__ __align__(16) float fJ[128];
    __shared__ float2 s2[128][17];

    const int tid = threadIdx.x;
    const int r = tid >> 4, c = tid & 15;

    if (tid < 128) fI[tid] = g_fused[b * 2304 + I * 128 + tid];
    else           fJ[tid - 128] = g_fused[b * 2304 + J * 128 + (tid - 128)];
    __syncthreads();

    ull fsl2[8], fs2[8], ft2[4];
#pragma unroll
    for (int i = 0; i < 8; i++) {
        float f = fI[r * 8 + i];
        fs2[i]  = pk2(f, f);
        fsl2[i] = pk2(f * LOG2E, f * LOG2E);
    }
#pragma unroll
    for (int m = 0; m < 4; m++)
        ft2[m] = pk2(fJ[c * 8 + 2 * m], fJ[c * 8 + 2 * m + 1]);

    ull nr2[8], dr2[8], nc2[4], dc2[4];
#pragma unroll
    for (int i = 0; i < 8; i++) { nr2[i] = 0ULL; dr2[i] = 0ULL; }
#pragma unroll
    for (int m = 0; m < 4; m++) { nc2[m] = 0ULL; dc2[m] = 0ULL; }

#pragma unroll
    for (int i = 0; i < 8; i++) {
#pragma unroll
        for (int m = 0; m < 4; m++) {
            ull p = mul2(fsl2[i], ft2[m]);
            float a0, a1; upk2(p, a0, a1);
            ull E2 = pk2(ex2f(a0), ex2f(a1));
            nr2[i] = fma2(E2, ft2[m], nr2[i]);
            dr2[i] = add2(dr2[i], E2);
            nc2[m] = fma2(E2, fs2[i], nc2[m]);
            dc2[m] = add2(dc2[m], E2);
        }
    }

#pragma unroll
    for (int i = 0; i < 8; i++) {
        float nx, ny, dx, dy;
        upk2(nr2[i], nx, ny);
        upk2(dr2[i], dx, dy);
        s2[r * 8 + i][c] = make_float2(nx + ny, dx + dy);
    }
    __syncthreads();
    if (tid < 128) {
        float2 a = s2[tid][0];
#pragma unroll
        for (int kk = 1; kk < 16; kk++) { float2 p = s2[tid][kk]; a.x += p.x; a.y += p.y; }
        float* dst = g_ap + (((size_t)(b * NT + I) * NT + J) * 128 + tid) * 2;
        dst[0] = a.x; dst[1] = a.y;
    }

    if (!diag) {
        __syncthreads();
#pragma unroll
        for (int m = 0; m < 4; m++) {
            float n0, n1, d0, d1;
            upk2(nc2[m], n0, n1);
            upk2(dc2[m], d0, d1);
            s2[c * 8 + 2 * m][r]     = make_float2(n0, d0);
            s2[c * 8 + 2 * m + 1][r] = make_float2(n1, d1);
        }
        __syncthreads();
        if (tid < 128) {
            float2 a = s2[tid][0];
#pragma unroll
            for (int kk = 1; kk < 16; kk++) { float2 p = s2[tid][kk]; a.x += p.x; a.y += p.y; }
            float* dst = g_ap + (((size_t)(b * NT + J) * NT + I) * 128 + tid) * 2;
            dst[0] = a.x; dst[1] = a.y;
        }
    }
}

// ---------------------------------------------------------------------------
// Kernel 3: split-K shared projections. grid (PROJ_KC, 4, 3), block 128.
// Output layout [task][kc][b][j]: store coalesced across j per batch.
// ---------------------------------------------------------------------------
__global__ void shared_proj_split(const float* __restrict__ sent,
                                  const float* __restrict__ Wsh) {
    const int kc   = blockIdx.x;
    const int jt   = blockIdx.y;
    const int task = blockIdx.z;
    const int j    = jt * 128 + threadIdx.x;      // 0..511
    const int i0   = kc * PROJ_KCH;

    __shared__ __align__(16) float xs[PROJ_KCH][36];

    for (int e = threadIdx.x; e < PROJ_KCH * 32; e += 128) {
        int b = e & 31, i = e >> 5;
        xs[i][b] = (task == 0) ? sent[b * 768 + i0 + i]
                               : g_fused[b * 2304 + 768 * task + i0 + i];
    }
    __syncthreads();

    float acc[32];
#pragma unroll
    for (int b = 0; b < 32; b++) acc[b] = 0.f;

#pragma unroll
    for (int i = 0; i < PROJ_KCH; i++) {
        float w = Wsh[(i0 + i) * 512 + j];
#pragma unroll
        for (int b4 = 0; b4 < 8; b4++) {
            float4 x = *reinterpret_cast<const float4*>(&xs[i][b4 * 4]);
            acc[b4 * 4 + 0] = fmaf(x.x, w, acc[b4 * 4 + 0]);
            acc[b4 * 4 + 1] = fmaf(x.y, w, acc[b4 * 4 + 1]);
            acc[b4 * 4 + 2] = fmaf(x.z, w, acc[b4 * 4 + 2]);
            acc[b4 * 4 + 3] = fmaf(x.w, w, acc[b4 * 4 + 3]);
        }
    }

#pragma unroll
    for (int b = 0; b < 32; b++)
        g_pp[(((size_t)task * PROJ_KC + kc) * 32 + b) * 512 + j] = acc[b];
}

// ---------------------------------------------------------------------------
// Kernel 4: gather — reduce attn + proj partials into g_finalT[i][b].
// grid (15, 32): blockIdx.y = batch, i-chunk of 256. Coalesced reads;
// scattered 4B writes (cheap: 0.5MB useful).
// ---------------------------------------------------------------------------
__global__ void gather_kernel(const float* __restrict__ bsh) {
    const int b = blockIdx.y;
    const int i = blockIdx.x * 256 + threadIdx.x;   // 0..3839

    float val;
    if (i < 2304) {
        const int T = i >> 7, row = i & 127;
        const float2* ap = reinterpret_cast<const float2*>(g_ap)
                         + ((size_t)(b * NT + T) * NT) * 128 + row;
        float num = 0.f, den = 0.f;
#pragma unroll
        for (int s = 0; s < NT; s++) { float2 p = ap[s * 128]; num += p.x; den += p.y; }
        val = num / den;
    } else {
        const int t = i - 2304;
        const int task = t >> 9, jj = t & 511;
        float a = bsh[jj];
        const float* pp = g_pp + (((size_t)task * PROJ_KC) * 32 + b) * 512 + jj;
#pragma unroll
        for (int s = 0; s < PROJ_KC; s++) a += pp[(size_t)s * 32 * 512];
        val = a;
    }
    g_finalT[(size_t)i * 32 + b] = val;
}

// ---------------------------------------------------------------------------
// Kernel 5: split-K mlp1 from compact g_finalT.  grid MLP_KC, block 256.
// ---------------------------------------------------------------------------
__global__ void __launch_bounds__(256) mlp1_split(const float* __restrict__ W1) {
    const int kc = blockIdx.x;
    const int i0 = kc * MLP_KCH;
    const int j  = threadIdx.x;

    __shared__ __align__(16) float xs[MLP_KCH][36];

    for (int e = threadIdx.x; e < MLP_KCH * 32; e += 256) {
        int ii = e >> 5, b = e & 31;
        xs[ii][b] = g_finalT[(size_t)(i0 + ii) * 32 + b];   // coalesced
    }
    __syncthreads();

    float acc[32];
#pragma unroll
    for (int b = 0; b < 32; b++) acc[b] = 0.f;

#pragma unroll
    for (int i = 0; i < MLP_KCH; i++) {
        float w = W1[(i0 + i) * 256 + j];
#pragma unroll
        for (int b4 = 0; b4 < 8; b4++) {
            float4 x = *reinterpret_cast<const float4*>(&xs[i][b4 * 4]);
            acc[b4 * 4 + 0] = fmaf(x.x, w, acc[b4 * 4 + 0]);
            acc[b4 * 4 + 1] = fmaf(x.y, w, acc[b4 * 4 + 1]);
            acc[b4 * 4 + 2] = fmaf(x.z, w, acc[b4 * 4 + 2]);
            acc[b4 * 4 + 3] = fmaf(x.w, w, acc[b4 * 4 + 3]);
        }
    }

#pragma unroll
    for (int b = 0; b < 32; b++)
        g_h_part[((size_t)kc * 32 + b) * 256 + j] = acc[b];
}

// ---------------------------------------------------------------------------
// Kernel 6: reduce mlp1 partials + bias + relu, then mlp2 + sigmoid.
// grid 32 (batch), block 256 (j).
// ---------------------------------------------------------------------------
__global__ void mlp_tail(const float* __restrict__ b1,
                         const float* __restrict__ W2,
                         const float* __restrict__ b2,
                         float* __restrict__ out) {
    const int b = blockIdx.x;
    const int j = threadIdx.x;

    float a0 = b1[j], a1 = 0.f, a2 = 0.f, a3 = 0.f;
#pragma unroll 6
    for (int kc = 0; kc < MLP_KC; kc += 4) {
        a0 += g_h_part[((size_t)(kc + 0) * 32 + b) * 256 + j];
        a1 += g_h_part[((size_t)(kc + 1) * 32 + b) * 256 + j];
        a2 += g_h_part[((size_t)(kc + 2) * 32 + b) * 256 + j];
        a3 += g_h_part[((size_t)(kc + 3) * 32 + b) * 256 + j];
    }
    __shared__ float h[256];
    h[j] = fmaxf((a0 + a1) + (a2 + a3), 0.f);
    __syncthreads();

    const int w = j >> 5, lane = j & 31;
    if (w < 7) {
        float s = 0.f;
#pragma unroll
        for (int q = 0; q < 8; q++) s = fmaf(h[q * 32 + lane], W2[(q * 32 + lane) * 7 + w], s);
#pragma unroll
        for (int o = 16; o > 0; o >>= 1) s += __shfl_xor_sync(0xffffffffu, s, o);
        if (lane == 0) out[b * 7 + w] = 1.f / (1.f + __expf(-(s + b2[w])));
    }
}

extern "C" void kernel_launch(void* const* d_in, const int* in_sizes, int n_in,
                              void* d_out, int out_size) {
    const float* sent = (const float*)d_in[0];
    const float* ts   = (const float*)d_in[1];
    const float* oth  = (const float*)d_in[2];
    const float* sd   = (const float*)d_in[3];
    const float* ss   = (const float*)d_in[4];
    const float* Wsh  = (const float*)d_in[5];
    const float* bsh  = (const float*)d_in[6];
    const float* W1   = (const float*)d_in[7];
    const float* b1   = (const float*)d_in[8];
    const float* W2   = (const float*)d_in[9];
    const float* b2   = (const float*)d_in[10];
    float* out = (float*)d_out;

    static cudaStream_t s1 = nullptr;
    static cudaEvent_t ev_pre = nullptr, ev_sym = nullptr;
    if (s1 == nullptr) {
        cudaStreamCreateWithFlags(&s1, cudaStreamNonBlocking);
        cudaEventCreateWithFlags(&ev_pre, cudaEventDisableTiming);
        cudaEventCreateWithFlags(&ev_sym, cudaEventDisableTiming);
    }

    attn_pre_kernel<<<dim3(3, 32, 3), 256>>>(sent, ts, oth, sd, ss);
    cudaEventRecord(ev_pre, 0);
    cudaStreamWaitEvent(s1, ev_pre, 0);
    attn_fused_sym<<<dim3(NT, NT, 32), 256, 0, s1>>>();
    cudaEventRecord(ev_sym, s1);
    shared_proj_split<<<dim3(PROJ_KC, 4, 3), 128>>>(sent, Wsh);   // overlaps sym
    cudaStreamWaitEvent(0, ev_sym, 0);
    gather_kernel<<<dim3(15, 32), 256>>>(bsh);
    mlp1_split<<<MLP_KC, 256>>>(W1);
    mlp_tail<<<32, 256>>>(b1, W2, b2, out);
}

// round 7
// speedup vs baseline: 1.9987x; 1.6246x over previous
#include <cuda_runtime.h>

#define LOG2E 1.4426950408889634f
#define NI 20                 // intervals per attention
#define NNODE 9               // Chebyshev nodes per interval (degree 8)
#define NODES (NI * NNODE)    // 180
#define NCHUNK 8              // t-chunks for fused node eval

#define PROJ_KC 24            // 768 / 32
#define PROJ_KCH 32
#define MLP_KC 120            // 3840 / 32
#define MLP_KCH 32

// ---------------- scratch (__device__ globals; allocation-free rule) -------
__device__ float g_fused[32 * 2304];                 // [sentence | scene | speaker]
__device__ float g_finalT[3840 * 32];                // transposed final [i][b]
__device__ float g_h_part[MLP_KC * 32 * 256];        // mlp1 partials [kc][b][j]
__device__ float g_pp[3 * PROJ_KC * 32 * 512];       // proj partials [task][kc][b][j]
__device__ float g_np[32 * NCHUNK * NODES * 2];      // fused node partials [b][chunk][node][num,den]
__device__ float g_frange[32 * 2];                   // fused range [b][min,max]

__constant__ float CHEB[9] = {1.f, 0.92387953f, 0.70710678f, 0.38268343f, 0.f,
                              -0.38268343f, -0.70710678f, -0.92387953f, -1.f};
__constant__ float LAMB[9] = {0.5f, -1.f, 1.f, -1.f, 1.f, -1.f, 1.f, -1.f, 0.5f};

__device__ __forceinline__ float ex2f(float x) {
    float y; asm("ex2.approx.f32 %0, %1;" : "=f"(y) : "f"(x)); return y;
}
__device__ __forceinline__ float wredsum(float v) {
#pragma unroll
    for (int o = 16; o > 0; o >>= 1) v += __shfl_xor_sync(0xffffffffu, v, o);
    return v;
}

// Barycentric evaluation at x from node tables (num, den share weights).
__device__ __forceinline__ float interp_eval(float x, float xmin, float w, float hw,
                                             float invw,
                                             const float* __restrict__ snum,
                                             const float* __restrict__ sden) {
    int c = (int)((x - xmin) * invw);
    c = (c < 0) ? 0 : ((c >= NI) ? NI - 1 : c);
    const float x0 = xmin + (c + 0.5f) * w;
    const int base = c * NNODE;
    float wn = 0.f, wd = 0.f;
    float hitn = 0.f, hitd = 1.f;
    bool hit = false;
#pragma unroll
    for (int m = 0; m < NNODE; m++) {
        float xm = x0 + hw * CHEB[m];
        float d = x - xm;
        if (fabsf(d) < 1e-10f) { hit = true; hitn = snum[base + m]; hitd = sden[base + m]; d = 1.f; }
        float wm = __fdividef(LAMB[m], d);
        wn = fmaf(wm, snum[base + m], wn);
        wd = fmaf(wm, sden[base + m], wd);
    }
    return hit ? __fdividef(hitn, hitd) : __fdividef(wn, wd);
}

// ---------------------------------------------------------------------------
// Kernel 1: the two S=768 attentions via Chebyshev node eval + interpolation,
// plus sentence copy. grid (32, 3) = (batch, task), block 256.
// task 0: attn(q=oth,k=ts,v=ts) -> g_fused[b][1536+s]
// task 1: attn(q=ss, k=ss,v=sd) -> g_fused[b][ 768+s]
// task 2: copy sentence         -> g_fused[b][      s]
// ---------------------------------------------------------------------------
__global__ void __launch_bounds__(256) attn_pre_interp(const float* __restrict__ sent,
                                                       const float* __restrict__ ts,
                                                       const float* __restrict__ oth,
                                                       const float* __restrict__ sd,
                                                       const float* __restrict__ ss) {
    const int b = blockIdx.x, task = blockIdx.y;
    const int tid = threadIdx.x, lane = tid & 31, wid = tid >> 5;

    if (task == 2) {
        for (int i = tid; i < 768; i += 256) g_fused[b * 2304 + i] = sent[b * 768 + i];
        return;
    }

    const float* q = (task == 0) ? oth : ss;
    const float* k = (task == 0) ? ts  : ss;
    const float* v = (task == 0) ? ts  : sd;
    const int outoff = (task == 0) ? 1536 : 768;

    __shared__ __align__(16) float sq[768], sk[768], sv[768];
    __shared__ float snum[NODES], sden[NODES];
    __shared__ float red[16];

    for (int i = tid; i < 768; i += 256) {
        sq[i] = q[b * 768 + i];
        sk[i] = k[b * 768 + i];
        sv[i] = v[b * 768 + i];
    }
    __syncthreads();

    // range of q
    float lmin = 1e30f, lmax = -1e30f;
    for (int i = tid; i < 768; i += 256) {
        float x = sq[i];
        lmin = fminf(lmin, x); lmax = fmaxf(lmax, x);
    }
#pragma unroll
    for (int o = 16; o > 0; o >>= 1) {
        lmin = fminf(lmin, __shfl_xor_sync(0xffffffffu, lmin, o));
        lmax = fmaxf(lmax, __shfl_xor_sync(0xffffffffu, lmax, o));
    }
    if (lane == 0) { red[wid] = lmin; red[8 + wid] = lmax; }
    __syncthreads();
    float xmin = red[0], xmax = red[8];
#pragma unroll
    for (int i = 1; i < 8; i++) { xmin = fminf(xmin, red[i]); xmax = fmaxf(xmax, red[8 + i]); }

    const float w  = (xmax - xmin) * (1.f / NI);
    const float hw = 0.5f * w;

    // node evaluation: warp wid handles nodes wid, wid+8, ...
    for (int m = wid; m < NODES; m += 8) {
        const int c = m / NNODE, mm = m - c * NNODE;
        const float X  = xmin + (c + 0.5f) * w + hw * CHEB[mm];
        const float Xl = X * LOG2E;
        float sn = 0.f, sd_ = 0.f;
        for (int t = lane; t < 768; t += 32) {
            float e = ex2f(Xl * sk[t]);
            sd_ += e;
            sn = fmaf(e, sv[t], sn);
        }
        sn = wredsum(sn); sd_ = wredsum(sd_);
        if (lane == 0) { snum[m] = sn; sden[m] = sd_; }
    }
    __syncthreads();

    const float invw = __fdividef(1.f, w);
    for (int s = tid; s < 768; s += 256)
        g_fused[b * 2304 + outoff + s] = interp_eval(sq[s], xmin, w, hw, invw, snum, sden);
}

// ---------------------------------------------------------------------------
// Kernel 2: fused-attention node partials. grid (NCHUNK, 32), block 256.
// q=k=v=g_fused[b]. Each block: full range reduce (identical across chunks,
// deterministic) + node sums over its 288-term t-chunk.
// ---------------------------------------------------------------------------
__global__ void __launch_bounds__(256) fused_nodes() {
    const int chunk = blockIdx.x, b = blockIdx.y;
    const int tid = threadIdx.x, lane = tid & 31, wid = tid >> 5;

    __shared__ __align__(16) float sf[2304];
    __shared__ float red[16];

    for (int i = tid; i < 2304; i += 256) sf[i] = g_fused[b * 2304 + i];
    __syncthreads();

    float lmin = 1e30f, lmax = -1e30f;
    for (int i = tid; i < 2304; i += 256) {
        float x = sf[i];
        lmin = fminf(lmin, x); lmax = fmaxf(lmax, x);
    }
#pragma unroll
    for (int o = 16; o > 0; o >>= 1) {
        lmin = fminf(lmin, __shfl_xor_sync(0xffffffffu, lmin, o));
        lmax = fmaxf(lmax, __shfl_xor_sync(0xffffffffu, lmax, o));
    }
    if (lane == 0) { red[wid] = lmin; red[8 + wid] = lmax; }
    __syncthreads();
    float xmin = red[0], xmax = red[8];
#pragma unroll
    for (int i = 1; i < 8; i++) { xmin = fminf(xmin, red[i]); xmax = fmaxf(xmax, red[8 + i]); }

    if (chunk == 0 && tid == 0) { g_frange[b * 2] = xmin; g_frange[b * 2 + 1] = xmax; }

    const float w  = (xmax - xmin) * (1.f / NI);
    const float hw = 0.5f * w;
    const int t0 = chunk * 288;

    for (int m = wid; m < NODES; m += 8) {
        const int c = m / NNODE, mm = m - c * NNODE;
        const float X  = xmin + (c + 0.5f) * w + hw * CHEB[mm];
        const float Xl = X * LOG2E;
        float sn = 0.f, sd_ = 0.f;
        for (int t = t0 + lane; t < t0 + 288; t += 32) {
            float f = sf[t];
            float e = ex2f(Xl * f);
            sd_ += e;
            sn = fmaf(e, f, sn);   // v == f
        }
        sn = wredsum(sn); sd_ = wredsum(sd_);
        if (lane == 0) {
            float* dst = g_np + ((size_t)(b * NCHUNK + chunk) * NODES + m) * 2;
            dst[0] = sn; dst[1] = sd_;
        }
    }
}

// ---------------------------------------------------------------------------
// Kernel 3: split-K shared projections. grid (PROJ_KC, 4, 3), block 128.
// Output layout [task][kc][b][j].
// ---------------------------------------------------------------------------
__global__ void shared_proj_split(const float* __restrict__ sent,
                                  const float* __restrict__ Wsh) {
    const int kc   = blockIdx.x;
    const int jt   = blockIdx.y;
    const int task = blockIdx.z;
    const int j    = jt * 128 + threadIdx.x;      // 0..511
    const int i0   = kc * PROJ_KCH;

    __shared__ __align__(16) float xs[PROJ_KCH][36];

    for (int e = threadIdx.x; e < PROJ_KCH * 32; e += 128) {
        int b = e & 31, i = e >> 5;
        xs[i][b] = (task == 0) ? sent[b * 768 + i0 + i]
                               : g_fused[b * 2304 + 768 * task + i0 + i];
    }
    __syncthreads();

    float acc[32];
#pragma unroll
    for (int b = 0; b < 32; b++) acc[b] = 0.f;

#pragma unroll
    for (int i = 0; i < PROJ_KCH; i++) {
        float w = Wsh[(i0 + i) * 512 + j];
#pragma unroll
        for (int b4 = 0; b4 < 8; b4++) {
            float4 x = *reinterpret_cast<const float4*>(&xs[i][b4 * 4]);
            acc[b4 * 4 + 0] = fmaf(x.x, w, acc[b4 * 4 + 0]);
            acc[b4 * 4 + 1] = fmaf(x.y, w, acc[b4 * 4 + 1]);
            acc[b4 * 4 + 2] = fmaf(x.z, w, acc[b4 * 4 + 2]);
            acc[b4 * 4 + 3] = fmaf(x.w, w, acc[b4 * 4 + 3]);
        }
    }

#pragma unroll
    for (int b = 0; b < 32; b++)
        g_pp[(((size_t)task * PROJ_KC + kc) * 32 + b) * 512 + j] = acc[b];
}

// ---------------------------------------------------------------------------
// Kernel 4: gather. grid (15, 32), block 256.
// blocks x<9: reduce node partials + interpolate z_s. blocks x>=9: proj reduce.
// Writes g_finalT[i][b].
// ---------------------------------------------------------------------------
__global__ void __launch_bounds__(256) gather_kernel(const float* __restrict__ bsh) {
    const int b = blockIdx.y;
    const int i = blockIdx.x * 256 + threadIdx.x;   // 0..3839

    float val;
    if (blockIdx.x < 9) {
        __shared__ float snum[NODES], sden[NODES];
        for (int m = threadIdx.x; m < NODES; m += 256) {
            float n = 0.f, d = 0.f;
#pragma unroll
            for (int ch = 0; ch < NCHUNK; ch++) {
                const float* p = g_np + ((size_t)(b * NCHUNK + ch) * NODES + m) * 2;
                n += p[0]; d += p[1];
            }
            snum[m] = n; sden[m] = d;
        }
        __syncthreads();
        const float xmin = g_frange[b * 2], xmax = g_frange[b * 2 + 1];
        const float w  = (xmax - xmin) * (1.f / NI);
        const float hw = 0.5f * w;
        const float invw = __fdividef(1.f, w);
        const float x = g_fused[b * 2304 + i];
        val = interp_eval(x, xmin, w, hw, invw, snum, sden);
    } else {
        const int t = i - 2304;
        const int task = t >> 9, jj = t & 511;
        float a = bsh[jj];
        const float* pp = g_pp + (((size_t)task * PROJ_KC) * 32 + b) * 512 + jj;
#pragma unroll
        for (int s = 0; s < PROJ_KC; s++) a += pp[(size_t)s * 32 * 512];
        val = a;
    }
    g_finalT[(size_t)i * 32 + b] = val;
}

// ---------------------------------------------------------------------------
// Kernel 5: split-K mlp1 from compact g_finalT. grid MLP_KC, block 256.
// ---------------------------------------------------------------------------
__global__ void __launch_bounds__(256) mlp1_split(const float* __restrict__ W1) {
    const int kc = blockIdx.x;
    const int i0 = kc * MLP_KCH;
    const int j  = threadIdx.x;

    __shared__ __align__(16) float xs[MLP_KCH][36];

    for (int e = threadIdx.x; e < MLP_KCH * 32; e += 256) {
        int ii = e >> 5, b = e & 31;
        xs[ii][b] = g_finalT[(size_t)(i0 + ii) * 32 + b];   // coalesced
    }
    __syncthreads();

    float acc[32];
#pragma unroll
    for (int b = 0; b < 32; b++) acc[b] = 0.f;

#pragma unroll
    for (int i = 0; i < MLP_KCH; i++) {
        float w = W1[(i0 + i) * 256 + j];
#pragma unroll
        for (int b4 = 0; b4 < 8; b4++) {
            float4 x = *reinterpret_cast<const float4*>(&xs[i][b4 * 4]);
            acc[b4 * 4 + 0] = fmaf(x.x, w, acc[b4 * 4 + 0]);
            acc[b4 * 4 + 1] = fmaf(x.y, w, acc[b4 * 4 + 1]);
            acc[b4 * 4 + 2] = fmaf(x.z, w, acc[b4 * 4 + 2]);
            acc[b4 * 4 + 3] = fmaf(x.w, w, acc[b4 * 4 + 3]);
        }
    }

#pragma unroll
    for (int b = 0; b < 32; b++)
        g_h_part[((size_t)kc * 32 + b) * 256 + j] = acc[b];
}

// ---------------------------------------------------------------------------
// Kernel 6: reduce mlp1 partials + bias + relu, then mlp2 + sigmoid.
// grid 32 (batch), block 256 (j).
// ---------------------------------------------------------------------------
__global__ void mlp_tail(const float* __restrict__ b1,
                         const float* __restrict__ W2,
                         const float* __restrict__ b2,
                         float* __restrict__ out) {
    const int b = blockIdx.x;
    const int j = threadIdx.x;

    float a0 = b1[j], a1 = 0.f, a2 = 0.f, a3 = 0.f;
#pragma unroll 6
    for (int kc = 0; kc < MLP_KC; kc += 4) {
        a0 += g_h_part[((size_t)(kc + 0) * 32 + b) * 256 + j];
        a1 += g_h_part[((size_t)(kc + 1) * 32 + b) * 256 + j];
        a2 += g_h_part[((size_t)(kc + 2) * 32 + b) * 256 + j];
        a3 += g_h_part[((size_t)(kc + 3) * 32 + b) * 256 + j];
    }
    __shared__ float h[256];
    h[j] = fmaxf((a0 + a1) + (a2 + a3), 0.f);
    __syncthreads();

    const int w = j >> 5, lane = j & 31;
    if (w < 7) {
        float s = 0.f;
#pragma unroll
        for (int q = 0; q < 8; q++) s = fmaf(h[q * 32 + lane], W2[(q * 32 + lane) * 7 + w], s);
#pragma unroll
        for (int o = 16; o > 0; o >>= 1) s += __shfl_xor_sync(0xffffffffu, s, o);
        if (lane == 0) out[b * 7 + w] = 1.f / (1.f + __expf(-(s + b2[w])));
    }
}

extern "C" void kernel_launch(void* const* d_in, const int* in_sizes, int n_in,
                              void* d_out, int out_size) {
    const float* sent = (const float*)d_in[0];
    const float* ts   = (const float*)d_in[1];
    const float* oth  = (const float*)d_in[2];
    const float* sd   = (const float*)d_in[3];
    const float* ss   = (const float*)d_in[4];
    const float* Wsh  = (const float*)d_in[5];
    const float* bsh  = (const float*)d_in[6];
    const float* W1   = (const float*)d_in[7];
    const float* b1   = (const float*)d_in[8];
    const float* W2   = (const float*)d_in[9];
    const float* b2   = (const float*)d_in[10];
    float* out = (float*)d_out;

    static cudaStream_t s1 = nullptr;
    static cudaEvent_t ev_pre = nullptr, ev_proj = nullptr;
    if (s1 == nullptr) {
        cudaStreamCreateWithFlags(&s1, cudaStreamNonBlocking);
        cudaEventCreateWithFlags(&ev_pre, cudaEventDisableTiming);
        cudaEventCreateWithFlags(&ev_proj, cudaEventDisableTiming);
    }

    attn_pre_interp<<<dim3(32, 3), 256>>>(sent, ts, oth, sd, ss);
    cudaEventRecord(ev_pre, 0);
    cudaStreamWaitEvent(s1, ev_pre, 0);
    shared_proj_split<<<dim3(PROJ_KC, 4, 3), 128, 0, s1>>>(sent, Wsh);  // overlaps fused_nodes
    cudaEventRecord(ev_proj, s1);
    fused_nodes<<<dim3(NCHUNK, 32), 256>>>();
    cudaStreamWaitEvent(0, ev_proj, 0);
    gather_kernel<<<dim3(15, 32), 256>>>(bsh);
    mlp1_split<<<MLP_KC, 256>>>(W1);
    mlp_tail<<<32, 256>>>(b1, W2, b2, out);
}

// round 8
// speedup vs baseline: 2.9971x; 1.4995x over previous
#include <cuda_runtime.h>

#define LOG2E 1.4426950408889634f
#define NI 12                 // intervals per attention
#define NNODE 9               // Chebyshev nodes per interval (degree 8)
#define NODES (NI * NNODE)    // 108
#define NGRP 6                // node-groups for fused node eval (18 nodes each)

#define PROJ_KC 24            // 768 / 32
#define PROJ_KCH 32
#define MLP_KC 120            // 3840 / 32
#define MLP_KCH 32

#define FAT_NODE_BLOCKS (NGRP * 32)            // 192
#define FAT_PROJ_BLOCKS (PROJ_KC * 2 * 3)      // 144

// ---------------- scratch (__device__ globals; allocation-free rule) -------
__device__ float  g_fused[32 * 2304];            // [sentence | scene | speaker]
__device__ float  g_h_part[MLP_KC * 32 * 256];   // mlp1 partials [kc][b][j]
__device__ float  g_pp[3 * PROJ_KC * 32 * 512];  // proj partials [task][kc][b][j]
__device__ float2 g_nodes[32 * NODES];           // fused node table [b][m] (num,den)
__device__ float  g_frange[32 * 2];              // fused range [b][min,max]

__constant__ float CHEB[9] = {1.f, 0.92387953f, 0.70710678f, 0.38268343f, 0.f,
                              -0.38268343f, -0.70710678f, -0.92387953f, -1.f};
__constant__ float LAMB[9] = {0.5f, -1.f, 1.f, -1.f, 1.f, -1.f, 1.f, -1.f, 0.5f};

__device__ __forceinline__ float ex2f(float x) {
    float y; asm("ex2.approx.f32 %0, %1;" : "=f"(y) : "f"(x)); return y;
}
__device__ __forceinline__ float wredsum(float v) {
#pragma unroll
    for (int o = 16; o > 0; o >>= 1) v += __shfl_xor_sync(0xffffffffu, v, o);
    return v;
}

// Barycentric eval from shared-memory node tables.
__device__ __forceinline__ float interp_s(float x, float xmin, float w, float hw,
                                          float invw,
                                          const float* __restrict__ snum,
                                          const float* __restrict__ sden) {
    int c = (int)((x - xmin) * invw);
    c = (c < 0) ? 0 : ((c >= NI) ? NI - 1 : c);
    const float x0 = xmin + (c + 0.5f) * w;
    const int base = c * NNODE;
    float wn = 0.f, wd = 0.f, hitn = 0.f, hitd = 1.f;
    bool hit = false;
#pragma unroll
    for (int m = 0; m < NNODE; m++) {
        float d = x - (x0 + hw * CHEB[m]);
        if (fabsf(d) < 1e-10f) { hit = true; hitn = snum[base + m]; hitd = sden[base + m]; d = 1.f; }
        float wm = __fdividef(LAMB[m], d);
        wn = fmaf(wm, snum[base + m], wn);
        wd = fmaf(wm, sden[base + m], wd);
    }
    return hit ? __fdividef(hitn, hitd) : __fdividef(wn, wd);
}

// Barycentric eval from global (L1/L2-resident) per-batch node table.
__device__ __forceinline__ float interp_g(float x, float xmin, float w, float hw,
                                          float invw,
                                          const float2* __restrict__ nodes) {
    int c = (int)((x - xmin) * invw);
    c = (c < 0) ? 0 : ((c >= NI) ? NI - 1 : c);
    const float x0 = xmin + (c + 0.5f) * w;
    const float2* nb = nodes + c * NNODE;
    float wn = 0.f, wd = 0.f, hitn = 0.f, hitd = 1.f;
    bool hit = false;
#pragma unroll
    for (int m = 0; m < NNODE; m++) {
        float2 nd = nb[m];
        float d = x - (x0 + hw * CHEB[m]);
        if (fabsf(d) < 1e-10f) { hit = true; hitn = nd.x; hitd = nd.y; d = 1.f; }
        float wm = __fdividef(LAMB[m], d);
        wn = fmaf(wm, nd.x, wn);
        wd = fmaf(wm, nd.y, wd);
    }
    return hit ? __fdividef(hitn, hitd) : __fdividef(wn, wd);
}

// ---------------------------------------------------------------------------
// Kernel 1: two S=768 attentions via node eval + interpolation, + sentence
// copy. grid (32, 3), block 512 (task 2 = copy uses first pass only).
// ---------------------------------------------------------------------------
__global__ void __launch_bounds__(512) attn_pre_interp(const float* __restrict__ sent,
                                                       const float* __restrict__ ts,
                                                       const float* __restrict__ oth,
                                                       const float* __restrict__ sd,
                                                       const float* __restrict__ ss) {
    const int b = blockIdx.x, task = blockIdx.y;
    const int tid = threadIdx.x, lane = tid & 31, wid = tid >> 5;

    if (task == 2) {
        for (int i = tid; i < 768; i += 512) g_fused[b * 2304 + i] = sent[b * 768 + i];
        return;
    }

    const float* q = (task == 0) ? oth : ss;
    const float* k = (task == 0) ? ts  : ss;
    const float* v = (task == 0) ? ts  : sd;
    const int outoff = (task == 0) ? 1536 : 768;

    __shared__ __align__(16) float sq[768], sk[768], sv[768];
    __shared__ float snum[NODES], sden[NODES];
    __shared__ float red[32];

    for (int i = tid; i < 768; i += 512) {
        sq[i] = q[b * 768 + i];
        sk[i] = k[b * 768 + i];
        sv[i] = v[b * 768 + i];
    }
    __syncthreads();

    float lmin = 1e30f, lmax = -1e30f;
    for (int i = tid; i < 768; i += 512) {
        float x = sq[i];
        lmin = fminf(lmin, x); lmax = fmaxf(lmax, x);
    }
#pragma unroll
    for (int o = 16; o > 0; o >>= 1) {
        lmin = fminf(lmin, __shfl_xor_sync(0xffffffffu, lmin, o));
        lmax = fmaxf(lmax, __shfl_xor_sync(0xffffffffu, lmax, o));
    }
    if (lane == 0) { red[wid] = lmin; red[16 + wid] = lmax; }
    __syncthreads();
    float xmin = red[0], xmax = red[16];
#pragma unroll
    for (int i = 1; i < 16; i++) { xmin = fminf(xmin, red[i]); xmax = fmaxf(xmax, red[16 + i]); }

    const float w  = (xmax - xmin) * (1.f / NI);
    const float hw = 0.5f * w;

    for (int m = wid; m < NODES; m += 16) {
        const int c = m / NNODE, mm = m - c * NNODE;
        const float Xl = (xmin + (c + 0.5f) * w + hw * CHEB[mm]) * LOG2E;
        float sn = 0.f, sd_ = 0.f;
        for (int t = lane; t < 768; t += 32) {
            float e = ex2f(Xl * sk[t]);
            sd_ += e;
            sn = fmaf(e, sv[t], sn);
        }
        sn = wredsum(sn); sd_ = wredsum(sd_);
        if (lane == 0) { snum[m] = sn; sden[m] = sd_; }
    }
    __syncthreads();

    const float invw = __fdividef(1.f, w);
    for (int s = tid; s < 768; s += 512)
        g_fused[b * 2304 + outoff + s] = interp_s(sq[s], xmin, w, hw, invw, snum, sden);
}

// ---------------------------------------------------------------------------
// Kernel 2 (fat): fused-attention node table + shared projections, one launch.
// blocks [0, 192): node eval — b = bx&31, grp = bx>>5; 18 nodes over full 2304.
// blocks [192, 336): proj split-K — 24 kc x 2 jt x 3 task, 256 j-cols each.
// ---------------------------------------------------------------------------
__global__ void __launch_bounds__(256) fat_kernel(const float* __restrict__ sent,
                                                  const float* __restrict__ Wsh) {
    const int bx = blockIdx.x;
    const int tid = threadIdx.x, lane = tid & 31, wid = tid >> 5;

    if (bx < FAT_NODE_BLOCKS) {
        const int b = bx & 31, grp = bx >> 5;

        __shared__ __align__(16) float sf[2304];
        __shared__ float red[16];

        for (int i = tid; i < 576; i += 256)
            *reinterpret_cast<float4*>(sf + i * 4) =
                *reinterpret_cast<const float4*>(g_fused + b * 2304 + i * 4);
        __syncthreads();

        float lmin = 1e30f, lmax = -1e30f;
        for (int i = tid; i < 2304; i += 256) {
            float x = sf[i];
            lmin = fminf(lmin, x); lmax = fmaxf(lmax, x);
        }
#pragma unroll
        for (int o = 16; o > 0; o >>= 1) {
            lmin = fminf(lmin, __shfl_xor_sync(0xffffffffu, lmin, o));
            lmax = fmaxf(lmax, __shfl_xor_sync(0xffffffffu, lmax, o));
        }
        if (lane == 0) { red[wid] = lmin; red[8 + wid] = lmax; }
        __syncthreads();
        float xmin = red[0], xmax = red[8];
#pragma unroll
        for (int i = 1; i < 8; i++) { xmin = fminf(xmin, red[i]); xmax = fmaxf(xmax, red[8 + i]); }

        if (grp == 0 && tid == 0) { g_frange[b * 2] = xmin; g_frange[b * 2 + 1] = xmax; }

        const float w  = (xmax - xmin) * (1.f / NI);
        const float hw = 0.5f * w;
        const int m0 = grp * (NODES / NGRP);          // 18 nodes per group

        for (int m = m0 + wid; m < m0 + NODES / NGRP; m += 8) {
            const int c = m / NNODE, mm = m - c * NNODE;
            const float Xl = (xmin + (c + 0.5f) * w + hw * CHEB[mm]) * LOG2E;
            float sn = 0.f, sd_ = 0.f;
            for (int t = lane; t < 2304; t += 32) {
                float f = sf[t];
                float e = ex2f(Xl * f);
                sd_ += e;
                sn = fmaf(e, f, sn);     // v == f
            }
            sn = wredsum(sn); sd_ = wredsum(sd_);
            if (lane == 0) g_nodes[b * NODES + m] = make_float2(sn, sd_);
        }
        return;
    }

    // ----- proj section -----
    const int p    = bx - FAT_NODE_BLOCKS;
    const int task = p / (PROJ_KC * 2);
    const int rem  = p - task * PROJ_KC * 2;
    const int kc   = rem >> 1;
    const int jt   = rem & 1;
    const int j    = jt * 256 + tid;       // 0..511
    const int i0   = kc * PROJ_KCH;

    __shared__ __align__(16) float xs[PROJ_KCH][36];

    for (int e = tid; e < PROJ_KCH * 32; e += 256) {
        int i = e & 31, b = e >> 5;        // coalesced reads (i fastest)
        xs[i][b] = (task == 0) ? sent[b * 768 + i0 + i]
                               : g_fused[b * 2304 + 768 * task + i0 + i];
    }
    __syncthreads();

    float acc[32];
#pragma unroll
    for (int b = 0; b < 32; b++) acc[b] = 0.f;

#pragma unroll
    for (int i = 0; i < PROJ_KCH; i++) {
        float wv = Wsh[(i0 + i) * 512 + j];
#pragma unroll
        for (int b4 = 0; b4 < 8; b4++) {
            float4 x = *reinterpret_cast<const float4*>(&xs[i][b4 * 4]);
            acc[b4 * 4 + 0] = fmaf(x.x, wv, acc[b4 * 4 + 0]);
            acc[b4 * 4 + 1] = fmaf(x.y, wv, acc[b4 * 4 + 1]);
            acc[b4 * 4 + 2] = fmaf(x.z, wv, acc[b4 * 4 + 2]);
            acc[b4 * 4 + 3] = fmaf(x.w, wv, acc[b4 * 4 + 3]);
        }
    }

#pragma unroll
    for (int b = 0; b < 32; b++)
        g_pp[(((size_t)task * PROJ_KC + kc) * 32 + b) * 512 + j] = acc[b];
}

// ---------------------------------------------------------------------------
// Kernel 3: mlp1 with fused assemble. grid MLP_KC (120), block 256.
// kc < 72: xs from z-interpolation (node table in L1/L2).
// kc >= 72: xs from proj partial reduce (coalesced jj-major).
// ---------------------------------------------------------------------------
__global__ void __launch_bounds__(256) mlp1_fused(const float* __restrict__ W1,
                                                  const float* __restrict__ bsh) {
    const int kc = blockIdx.x;
    const int i0 = kc * MLP_KCH;
    const int j  = threadIdx.x;

    __shared__ __align__(16) float xs[MLP_KCH][36];

    if (kc < 72) {
        for (int e = threadIdx.x; e < MLP_KCH * 32; e += 256) {
            int ii = e & 31, b = e >> 5;      // i fastest -> coalesced g_fused reads
            const float xmin = g_frange[b * 2], xmax = g_frange[b * 2 + 1];
            const float w  = (xmax - xmin) * (1.f / NI);
            const float hw = 0.5f * w;
            const float invw = __fdividef(1.f, w);
            const float x = g_fused[b * 2304 + i0 + ii];
            xs[ii][b] = interp_g(x, xmin, w, hw, invw, g_nodes + b * NODES);
        }
    } else {
        const int t0   = i0 - 2304;
        const int task = t0 >> 9;
        const int jj0  = t0 & 511;
        for (int e = threadIdx.x; e < MLP_KCH * 32; e += 256) {
            int jl = e & 31, b = e >> 5;      // jj fastest -> coalesced g_pp reads
            const int jj = jj0 + jl;
            float a = bsh[jj];
            const float* pp = g_pp + (((size_t)task * PROJ_KC) * 32 + b) * 512 + jj;
#pragma unroll
            for (int s = 0; s < PROJ_KC; s++) a += pp[(size_t)s * 32 * 512];
            xs[jl][b] = a;
        }
    }
    __syncthreads();

    float acc[32];
#pragma unroll
    for (int b = 0; b < 32; b++) acc[b] = 0.f;

#pragma unroll
    for (int i = 0; i < MLP_KCH; i++) {
        float w = W1[(i0 + i) * 256 + j];
#pragma unroll
        for (int b4 = 0; b4 < 8; b4++) {
            float4 x = *reinterpret_cast<const float4*>(&xs[i][b4 * 4]);
            acc[b4 * 4 + 0] = fmaf(x.x, w, acc[b4 * 4 + 0]);
            acc[b4 * 4 + 1] = fmaf(x.y, w, acc[b4 * 4 + 1]);
            acc[b4 * 4 + 2] = fmaf(x.z, w, acc[b4 * 4 + 2]);
            acc[b4 * 4 + 3] = fmaf(x.w, w, acc[b4 * 4 + 3]);
        }
    }

#pragma unroll
    for (int b = 0; b < 32; b++)
        g_h_part[((size_t)kc * 32 + b) * 256 + j] = acc[b];
}

// ---------------------------------------------------------------------------
// Kernel 4: reduce mlp1 partials + bias + relu, then mlp2 + sigmoid.
// grid 32 (batch), block 256 (j).
// ---------------------------------------------------------------------------
__global__ void mlp_tail(const float* __restrict__ b1,
                         const float* __restrict__ W2,
                         const float* __restrict__ b2,
                         float* __restrict__ out) {
    const int b = blockIdx.x;
    const int j = threadIdx.x;

    float a0 = b1[j], a1 = 0.f, a2 = 0.f, a3 = 0.f;
#pragma unroll 6
    for (int kc = 0; kc < MLP_KC; kc += 4) {
        a0 += g_h_part[((size_t)(kc + 0) * 32 + b) * 256 + j];
        a1 += g_h_part[((size_t)(kc + 1) * 32 + b) * 256 + j];
        a2 += g_h_part[((size_t)(kc + 2) * 32 + b) * 256 + j];
        a3 += g_h_part[((size_t)(kc + 3) * 32 + b) * 256 + j];
    }
    __shared__ float h[256];
    h[j] = fmaxf((a0 + a1) + (a2 + a3), 0.f);
    __syncthreads();

    const int w = j >> 5, lane = j & 31;
    if (w < 7) {
        float s = 0.f;
#pragma unroll
        for (int q = 0; q < 8; q++) s = fmaf(h[q * 32 + lane], W2[(q * 32 + lane) * 7 + w], s);
#pragma unroll
        for (int o = 16; o > 0; o >>= 1) s += __shfl_xor_sync(0xffffffffu, s, o);
        if (lane == 0) out[b * 7 + w] = 1.f / (1.f + __expf(-(s + b2[w])));
    }
}

extern "C" void kernel_launch(void* const* d_in, const int* in_sizes, int n_in,
                              void* d_out, int out_size) {
    const float* sent = (const float*)d_in[0];
    const float* ts   = (const float*)d_in[1];
    const float* oth  = (const float*)d_in[2];
    const float* sd   = (const float*)d_in[3];
    const float* ss   = (const float*)d_in[4];
    const float* Wsh  = (const float*)d_in[5];
    const float* bsh  = (const float*)d_in[6];
    const float* W1   = (const float*)d_in[7];
    const float* b1   = (const float*)d_in[8];
    const float* W2   = (const float*)d_in[9];
    const float* b2   = (const float*)d_in[10];
    float* out = (float*)d_out;

    attn_pre_interp<<<dim3(32, 3), 512>>>(sent, ts, oth, sd, ss);
    fat_kernel<<<FAT_NODE_BLOCKS + FAT_PROJ_BLOCKS, 256>>>(sent, Wsh);
    mlp1_fused<<<MLP_KC, 256>>>(W1, bsh);
    mlp_tail<<<32, 256>>>(b1, W2, b2, out);
}

// round 9
// speedup vs baseline: 3.1768x; 1.0600x over previous
#include <cuda_runtime.h>

#define LOG2E 1.4426950408889634f
#define NI 12                 // intervals per attention
#define NNODE 9               // Chebyshev nodes per interval (degree 8)
#define NODES (NI * NNODE)    // 108
#define NGRP 6                // node-groups for fused node eval (18 nodes each)

#define PROJ_KC 24            // 768 / 32
#define PROJ_KCH 32
#define MLP_KC 120            // 3840 / 32
#define MLP_KCH 32

#define FAT_NODE_BLOCKS (NGRP * 32)            // 192
#define FAT_PROJ_BLOCKS (PROJ_KC * 2 * 3)      // 144

// ---------------- scratch (__device__ globals; allocation-free rule) -------
__device__ float  g_fused[32 * 2304];            // [sentence | scene | speaker]
__device__ float  g_h_part[MLP_KC * 32 * 256];   // mlp1 partials [kc][b][j]
__device__ float  g_pp[3 * PROJ_KC * 32 * 512];  // proj partials [task][kc][b][j]
__device__ float2 g_nodes[32 * NODES];           // fused node table [b][m] (num,den)
__device__ float  g_frange[32 * 2];              // fused range [b][min,max]

__constant__ float CHEB[9] = {1.f, 0.92387953f, 0.70710678f, 0.38268343f, 0.f,
                              -0.38268343f, -0.70710678f, -0.92387953f, -1.f};
__constant__ float LAMB[9] = {0.5f, -1.f, 1.f, -1.f, 1.f, -1.f, 1.f, -1.f, 0.5f};

__device__ __forceinline__ float ex2f(float x) {
    float y; asm("ex2.approx.f32 %0, %1;" : "=f"(y) : "f"(x)); return y;
}
__device__ __forceinline__ float wredsum(float v) {
#pragma unroll
    for (int o = 16; o > 0; o >>= 1) v += __shfl_xor_sync(0xffffffffu, v, o);
    return v;
}

// Barycentric eval from shared-memory node tables.
__device__ __forceinline__ float interp_s(float x, float xmin, float w, float hw,
                                          float invw,
                                          const float* __restrict__ snum,
                                          const float* __restrict__ sden) {
    int c = (int)((x - xmin) * invw);
    c = (c < 0) ? 0 : ((c >= NI) ? NI - 1 : c);
    const float x0 = xmin + (c + 0.5f) * w;
    const int base = c * NNODE;
    float wn = 0.f, wd = 0.f, hitn = 0.f, hitd = 1.f;
    bool hit = false;
#pragma unroll
    for (int m = 0; m < NNODE; m++) {
        float d = x - (x0 + hw * CHEB[m]);
        if (fabsf(d) < 1e-10f) { hit = true; hitn = snum[base + m]; hitd = sden[base + m]; d = 1.f; }
        float wm = __fdividef(LAMB[m], d);
        wn = fmaf(wm, snum[base + m], wn);
        wd = fmaf(wm, sden[base + m], wd);
    }
    return hit ? __fdividef(hitn, hitd) : __fdividef(wn, wd);
}

// Barycentric eval from global (L1/L2-resident) per-batch node table.
__device__ __forceinline__ float interp_g(float x, float xmin, float w, float hw,
                                          float invw,
                                          const float2* __restrict__ nodes) {
    int c = (int)((x - xmin) * invw);
    c = (c < 0) ? 0 : ((c >= NI) ? NI - 1 : c);
    const float x0 = xmin + (c + 0.5f) * w;
    const float2* nb = nodes + c * NNODE;
    float wn = 0.f, wd = 0.f, hitn = 0.f, hitd = 1.f;
    bool hit = false;
#pragma unroll
    for (int m = 0; m < NNODE; m++) {
        float2 nd = nb[m];
        float d = x - (x0 + hw * CHEB[m]);
        if (fabsf(d) < 1e-10f) { hit = true; hitn = nd.x; hitd = nd.y; d = 1.f; }
        float wm = __fdividef(LAMB[m], d);
        wn = fmaf(wm, nd.x, wn);
        wd = fmaf(wm, nd.y, wd);
    }
    return hit ? __fdividef(hitn, hitd) : __fdividef(wn, wd);
}

// ---------------------------------------------------------------------------
// Kernel 1: two S=768 attentions via node eval + interpolation, + sentence
// copy. grid (32, 3), block 512.
// ---------------------------------------------------------------------------
__global__ void __launch_bounds__(512) attn_pre_interp(const float* __restrict__ sent,
                                                       const float* __restrict__ ts,
                                                       const float* __restrict__ oth,
                                                       const float* __restrict__ sd,
                                                       const float* __restrict__ ss) {
    const int b = blockIdx.x, task = blockIdx.y;
    const int tid = threadIdx.x, lane = tid & 31, wid = tid >> 5;

    if (task == 2) {
        for (int i = tid; i < 768; i += 512) g_fused[b * 2304 + i] = sent[b * 768 + i];
        return;
    }

    const float* q = (task == 0) ? oth : ss;
    const float* k = (task == 0) ? ts  : ss;
    const float* v = (task == 0) ? ts  : sd;
    const int outoff = (task == 0) ? 1536 : 768;

    __shared__ __align__(16) float sq[768], sk[768], sv[768];
    __shared__ float snum[NODES], sden[NODES];
    __shared__ float red[32];

    for (int i = tid; i < 768; i += 512) {
        sq[i] = q[b * 768 + i];
        sk[i] = k[b * 768 + i];
        sv[i] = v[b * 768 + i];
    }
    __syncthreads();

    float lmin = 1e30f, lmax = -1e30f;
    for (int i = tid; i < 768; i += 512) {
        float x = sq[i];
        lmin = fminf(lmin, x); lmax = fmaxf(lmax, x);
    }
#pragma unroll
    for (int o = 16; o > 0; o >>= 1) {
        lmin = fminf(lmin, __shfl_xor_sync(0xffffffffu, lmin, o));
        lmax = fmaxf(lmax, __shfl_xor_sync(0xffffffffu, lmax, o));
    }
    if (lane == 0) { red[wid] = lmin; red[16 + wid] = lmax; }
    __syncthreads();
    float xmin = red[0], xmax = red[16];
#pragma unroll
    for (int i = 1; i < 16; i++) { xmin = fminf(xmin, red[i]); xmax = fmaxf(xmax, red[16 + i]); }

    const float w  = (xmax - xmin) * (1.f / NI);
    const float hw = 0.5f * w;

    for (int m = wid; m < NODES; m += 16) {
        const int c = m / NNODE, mm = m - c * NNODE;
        const float Xl = (xmin + (c + 0.5f) * w + hw * CHEB[mm]) * LOG2E;
        float sn = 0.f, sd_ = 0.f;
        for (int t = lane; t < 768; t += 32) {
            float e = ex2f(Xl * sk[t]);
            sd_ += e;
            sn = fmaf(e, sv[t], sn);
        }
        sn = wredsum(sn); sd_ = wredsum(sd_);
        if (lane == 0) { snum[m] = sn; sden[m] = sd_; }
    }
    __syncthreads();

    const float invw = __fdividef(1.f, w);
    for (int s = tid; s < 768; s += 512)
        g_fused[b * 2304 + outoff + s] = interp_s(sq[s], xmin, w, hw, invw, snum, sden);
}

// ---------------------------------------------------------------------------
// Kernel 2 (fat): fused-attention node table + shared projections, one launch.
// blocks [0, 192): node eval — b = bx&31, grp = bx>>5; 18 nodes over full 2304.
// blocks [192, 336): proj split-K — 24 kc x 2 jt x 3 task, 256 j-cols each.
// ---------------------------------------------------------------------------
__global__ void __launch_bounds__(256) fat_kernel(const float* __restrict__ sent,
                                                  const float* __restrict__ Wsh) {
    const int bx = blockIdx.x;
    const int tid = threadIdx.x, lane = tid & 31, wid = tid >> 5;

    if (bx < FAT_NODE_BLOCKS) {
        const int b = bx & 31, grp = bx >> 5;

        __shared__ __align__(16) float sf[2304];
        __shared__ float red[16];

        for (int i = tid; i < 576; i += 256)
            *reinterpret_cast<float4*>(sf + i * 4) =
                *reinterpret_cast<const float4*>(g_fused + b * 2304 + i * 4);
        __syncthreads();

        float lmin = 1e30f, lmax = -1e30f;
        for (int i = tid; i < 2304; i += 256) {
            float x = sf[i];
            lmin = fminf(lmin, x); lmax = fmaxf(lmax, x);
        }
#pragma unroll
        for (int o = 16; o > 0; o >>= 1) {
            lmin = fminf(lmin, __shfl_xor_sync(0xffffffffu, lmin, o));
            lmax = fmaxf(lmax, __shfl_xor_sync(0xffffffffu, lmax, o));
        }
        if (lane == 0) { red[wid] = lmin; red[8 + wid] = lmax; }
        __syncthreads();
        float xmin = red[0], xmax = red[8];
#pragma unroll
        for (int i = 1; i < 8; i++) { xmin = fminf(xmin, red[i]); xmax = fmaxf(xmax, red[8 + i]); }

        if (grp == 0 && tid == 0) { g_frange[b * 2] = xmin; g_frange[b * 2 + 1] = xmax; }

        const float w  = (xmax - xmin) * (1.f / NI);
        const float hw = 0.5f * w;
        const int m0 = grp * (NODES / NGRP);          // 18 nodes per group

        for (int m = m0 + wid; m < m0 + NODES / NGRP; m += 8) {
            const int c = m / NNODE, mm = m - c * NNODE;
            const float Xl = (xmin + (c + 0.5f) * w + hw * CHEB[mm]) * LOG2E;
            float sn = 0.f, sd_ = 0.f;
            for (int t = lane; t < 2304; t += 32) {
                float f = sf[t];
                float e = ex2f(Xl * f);
                sd_ += e;
                sn = fmaf(e, f, sn);     // v == f
            }
            sn = wredsum(sn); sd_ = wredsum(sd_);
            if (lane == 0) g_nodes[b * NODES + m] = make_float2(sn, sd_);
        }
        return;
    }

    // ----- proj section -----
    const int p    = bx - FAT_NODE_BLOCKS;
    const int task = p / (PROJ_KC * 2);
    const int rem  = p - task * PROJ_KC * 2;
    const int kc   = rem >> 1;
    const int jt   = rem & 1;
    const int j    = jt * 256 + tid;       // 0..511
    const int i0   = kc * PROJ_KCH;

    __shared__ __align__(16) float xs[PROJ_KCH][36];

    for (int e = tid; e < PROJ_KCH * 32; e += 256) {
        int i = e & 31, b = e >> 5;        // coalesced reads (i fastest)
        xs[i][b] = (task == 0) ? sent[b * 768 + i0 + i]
                               : g_fused[b * 2304 + 768 * task + i0 + i];
    }
    __syncthreads();

    float acc[32];
#pragma unroll
    for (int b = 0; b < 32; b++) acc[b] = 0.f;

#pragma unroll
    for (int i = 0; i < PROJ_KCH; i++) {
        float wv = Wsh[(i0 + i) * 512 + j];
#pragma unroll
        for (int b4 = 0; b4 < 8; b4++) {
            float4 x = *reinterpret_cast<const float4*>(&xs[i][b4 * 4]);
            acc[b4 * 4 + 0] = fmaf(x.x, wv, acc[b4 * 4 + 0]);
            acc[b4 * 4 + 1] = fmaf(x.y, wv, acc[b4 * 4 + 1]);
            acc[b4 * 4 + 2] = fmaf(x.z, wv, acc[b4 * 4 + 2]);
            acc[b4 * 4 + 3] = fmaf(x.w, wv, acc[b4 * 4 + 3]);
        }
    }

#pragma unroll
    for (int b = 0; b < 32; b++)
        g_pp[(((size_t)task * PROJ_KC + kc) * 32 + b) * 512 + j] = acc[b];
}

// ---------------------------------------------------------------------------
// Kernel 3: mlp1 with fused assemble. grid MLP_KC (120), block 256.
// kc < 72: xs from z-interpolation (node table in L1/L2).
// kc >= 72: xs from proj partial reduce (coalesced jj-major).
// ---------------------------------------------------------------------------
__global__ void __launch_bounds__(256) mlp1_fused(const float* __restrict__ W1,
                                                  const float* __restrict__ bsh) {
    const int kc = blockIdx.x;
    const int i0 = kc * MLP_KCH;
    const int j  = threadIdx.x;

    __shared__ __align__(16) float xs[MLP_KCH][36];

    if (kc < 72) {
        for (int e = threadIdx.x; e < MLP_KCH * 32; e += 256) {
            int ii = e & 31, b = e >> 5;      // i fastest -> coalesced g_fused reads
            const float xmin = g_frange[b * 2], xmax = g_frange[b * 2 + 1];
            const float w  = (xmax - xmin) * (1.f / NI);
            const float hw = 0.5f * w;
            const float invw = __fdividef(1.f, w);
            const float x = g_fused[b * 2304 + i0 + ii];
            xs[ii][b] = interp_g(x, xmin, w, hw, invw, g_nodes + b * NODES);
        }
    } else {
        const int t0   = i0 - 2304;
        const int task = t0 >> 9;
        const int jj0  = t0 & 511;
        for (int e = threadIdx.x; e < MLP_KCH * 32; e += 256) {
            int jl = e & 31, b = e >> 5;      // jj fastest -> coalesced g_pp reads
            const int jj = jj0 + jl;
            float a = bsh[jj];
            const float* pp = g_pp + (((size_t)task * PROJ_KC) * 32 + b) * 512 + jj;
#pragma unroll
            for (int s = 0; s < PROJ_KC; s++) a += pp[(size_t)s * 32 * 512];
            xs[jl][b] = a;
        }
    }
    __syncthreads();

    float acc[32];
#pragma unroll
    for (int b = 0; b < 32; b++) acc[b] = 0.f;

#pragma unroll
    for (int i = 0; i < MLP_KCH; i++) {
        float w = W1[(i0 + i) * 256 + j];
#pragma unroll
        for (int b4 = 0; b4 < 8; b4++) {
            float4 x = *reinterpret_cast<const float4*>(&xs[i][b4 * 4]);
            acc[b4 * 4 + 0] = fmaf(x.x, w, acc[b4 * 4 + 0]);
            acc[b4 * 4 + 1] = fmaf(x.y, w, acc[b4 * 4 + 1]);
            acc[b4 * 4 + 2] = fmaf(x.z, w, acc[b4 * 4 + 2]);
            acc[b4 * 4 + 3] = fmaf(x.w, w, acc[b4 * 4 + 3]);
        }
    }

#pragma unroll
    for (int b = 0; b < 32; b++)
        g_h_part[((size_t)kc * 32 + b) * 256 + j] = acc[b];
}

// ---------------------------------------------------------------------------
// Kernel 4: reduce mlp1 partials + bias + relu, then mlp2 + sigmoid.
// grid 32 (batch), block 1024: tid>>8 = kc-quarter (30 partials, 6 accs),
// smem 4-way combine, then 7-warp mlp2 + sigmoid.
// ---------------------------------------------------------------------------
__global__ void __launch_bounds__(1024) mlp_tail(const float* __restrict__ b1,
                                                 const float* __restrict__ W2,
                                                 const float* __restrict__ b2,
                                                 float* __restrict__ out) {
    const int b = blockIdx.x;
    const int j = threadIdx.x & 255;
    const int qt = threadIdx.x >> 8;          // 0..3

    __shared__ float sred[4][256];
    __shared__ float h[256];

    const float* src = g_h_part + ((size_t)(qt * 30) * 32 + b) * 256 + j;
    float a0 = 0.f, a1 = 0.f, a2 = 0.f, a3 = 0.f, a4 = 0.f, a5 = 0.f;
#pragma unroll
    for (int i = 0; i < 30; i += 6) {
        a0 += src[(size_t)(i + 0) * 32 * 256];
        a1 += src[(size_t)(i + 1) * 32 * 256];
        a2 += src[(size_t)(i + 2) * 32 * 256];
        a3 += src[(size_t)(i + 3) * 32 * 256];
        a4 += src[(size_t)(i + 4) * 32 * 256];
        a5 += src[(size_t)(i + 5) * 32 * 256];
    }
    sred[qt][j] = ((a0 + a1) + (a2 + a3)) + (a4 + a5);
    __syncthreads();

    if (qt == 0) {
        float v = ((sred[0][j] + sred[1][j]) + (sred[2][j] + sred[3][j])) + b1[j];
        h[j] = fmaxf(v, 0.f);
    }
    __syncthreads();

    const int w = threadIdx.x >> 5, lane = threadIdx.x & 31;
    if (w < 7) {
        float s = 0.f;
#pragma unroll
        for (int q = 0; q < 8; q++) s = fmaf(h[q * 32 + lane], W2[(q * 32 + lane) * 7 + w], s);
#pragma unroll
        for (int o = 16; o > 0; o >>= 1) s += __shfl_xor_sync(0xffffffffu, s, o);
        if (lane == 0) out[b * 7 + w] = 1.f / (1.f + __expf(-(s + b2[w])));
    }
}

extern "C" void kernel_launch(void* const* d_in, const int* in_sizes, int n_in,
                              void* d_out, int out_size) {
    const float* sent = (const float*)d_in[0];
    const float* ts   = (const float*)d_in[1];
    const float* oth  = (const float*)d_in[2];
    const float* sd   = (const float*)d_in[3];
    const float* ss   = (const float*)d_in[4];
    const float* Wsh  = (const float*)d_in[5];
    const float* bsh  = (const float*)d_in[6];
    const float* W1   = (const float*)d_in[7];
    const float* b1   = (const float*)d_in[8];
    const float* W2   = (const float*)d_in[9];
    const float* b2   = (const float*)d_in[10];
    float* out = (float*)d_out;

    attn_pre_interp<<<dim3(32, 3), 512>>>(sent, ts, oth, sd, ss);
    fat_kernel<<<FAT_NODE_BLOCKS + FAT_PROJ_BLOCKS, 256>>>(sent, Wsh);
    mlp1_fused<<<MLP_KC, 256>>>(W1, bsh);
    mlp_tail<<<32, 1024>>>(b1, W2, b2, out);
}